// round 1
// baseline (speedup 1.0000x reference)
#include <cuda_runtime.h>
#include <math.h>

#define BB   8
#define TT   2048
#define CC   96
#define NH   3
#define HD   32
#define DFF  2048
#define HW   32
#define NKEY 65
#define EPSL 1e-5f

// ---- scratch (device globals; no allocation allowed) ----
__device__ float g_qkv[(size_t)BB * 3 * CC * TT];  // (B, 288, T): q rows 0..95, k 96..191, v 192..287
__device__ float g_ctx[(size_t)BB * CC * TT];      // attention context, feature-major
__device__ float g_h1 [(size_t)BB * CC * TT];      // post-LN1 hidden, feature-major

// =====================================================================
// Kernel 1: QKV projection  qkv[b,m,t] = sum_k W[m,k] * x[b,k,t] + bias[m]
// grid (T/128, 288/32, B), block 256.  Tile: 32 m-rows x 128 tokens, K=96.
// =====================================================================
__global__ __launch_bounds__(256) void k_qkv(const float* __restrict__ x,
                                             const float* __restrict__ w,
                                             const float* __restrict__ bias) {
    extern __shared__ float sm[];
    float* Ws = sm;            // [32][96]
    float* Xs = sm + 32 * 96;  // [96][128]
    __shared__ float Bs[32];

    int t0 = blockIdx.x * 128;
    int m0 = blockIdx.y * 32;
    int b  = blockIdx.z;
    int tid = threadIdx.x;

    for (int i = tid; i < 32 * 96; i += 256) Ws[i] = w[m0 * 96 + i];
    if (tid < 32) Bs[tid] = bias[m0 + tid];
    const float* xb = x + (size_t)b * CC * TT + t0;
    for (int i = tid; i < 96 * 128; i += 256) {
        int k = i >> 7, t = i & 127;
        Xs[k * 128 + t] = xb[(size_t)k * TT + t];
    }
    __syncthreads();

    int g = tid >> 5;    // 0..7 m-group
    int tl = tid & 31;   // lane -> token
    float acc[4][4];
#pragma unroll
    for (int i = 0; i < 4; i++)
#pragma unroll
        for (int j = 0; j < 4; j++) acc[i][j] = 0.f;

#pragma unroll 4
    for (int k = 0; k < 96; k++) {
        float wv[4], xv[4];
#pragma unroll
        for (int i = 0; i < 4; i++) wv[i] = Ws[(g + 8 * i) * 96 + k];
#pragma unroll
        for (int j = 0; j < 4; j++) xv[j] = Xs[k * 128 + tl + 32 * j];
#pragma unroll
        for (int i = 0; i < 4; i++)
#pragma unroll
            for (int j = 0; j < 4; j++) acc[i][j] += wv[i] * xv[j];
    }

    float* ob = g_qkv + (size_t)b * 3 * CC * TT + t0;
#pragma unroll
    for (int i = 0; i < 4; i++) {
        int m = m0 + g + 8 * i;
        float bv = Bs[g + 8 * i];
#pragma unroll
        for (int j = 0; j < 4; j++)
            ob[(size_t)m * TT + tl + 32 * j] = acc[i][j] + bv;
    }
}

// =====================================================================
// Kernel 2: banded attention.  grid (T/128, NH, B), block 128 (1 thread/query).
// Keys for query tile [t0, t0+127]: [t0-32, t0+159] -> 192 rows in smem.
// =====================================================================
__global__ __launch_bounds__(128) void k_attn() {
    extern __shared__ float sm[];
    float* Ks = sm;              // [192][33] padded
    float* Vs = Ks + 192 * 33;   // [192][33]
    float* Sc = Vs + 192 * 33;   // [128][65]

    int t0 = blockIdx.x * 128;
    int h  = blockIdx.y;
    int b  = blockIdx.z;
    int tid = threadIdx.x;

    const float* kb = g_qkv + (size_t)b * 3 * CC * TT + (size_t)(CC + h * HD) * TT;
    const float* vb = g_qkv + (size_t)b * 3 * CC * TT + (size_t)(2 * CC + h * HD) * TT;

    for (int r = tid; r < 192; r += 128) {
        int s = t0 - HW + r;
        bool ok = (s >= 0) && (s < TT);
#pragma unroll
        for (int d = 0; d < 32; d++) {
            Ks[r * 33 + d] = ok ? kb[(size_t)d * TT + s] : 0.f;
            Vs[r * 33 + d] = ok ? vb[(size_t)d * TT + s] : 0.f;
        }
    }
    __syncthreads();

    int t = t0 + tid;
    const float* qb = g_qkv + (size_t)b * 3 * CC * TT + (size_t)(h * HD) * TT + t;
    float q[32];
#pragma unroll
    for (int d = 0; d < 32; d++) q[d] = qb[(size_t)d * TT];

    const float scale = 0.17677669529663689f;  // 1/sqrt(32)
    float* scRow = Sc + tid * 65;
    float mx = -1e30f;
    for (int j = 0; j < NKEY; j++) {
        const float* kr = Ks + (tid + j) * 33;
        float a0 = 0.f, a1 = 0.f;
#pragma unroll
        for (int d = 0; d < 32; d += 2) {
            a0 += q[d] * kr[d];
            a1 += q[d + 1] * kr[d + 1];
        }
        float a = (a0 + a1) * scale;
        int s = t - HW + j;
        if (s < 0 || s >= TT) a = -1e30f;
        scRow[j] = a;
        mx = fmaxf(mx, a);
    }
    float sum = 0.f;
    for (int j = 0; j < NKEY; j++) {
        float e = __expf(scRow[j] - mx);
        scRow[j] = e;
        sum += e;
    }
    float inv = 1.f / sum;

    float ctx[32];
#pragma unroll
    for (int d = 0; d < 32; d++) ctx[d] = 0.f;
    for (int j = 0; j < NKEY; j++) {
        float p = scRow[j];
        const float* vr = Vs + (tid + j) * 33;
#pragma unroll
        for (int d = 0; d < 32; d++) ctx[d] += p * vr[d];
    }

    float* cb = g_ctx + (size_t)b * CC * TT + (size_t)(h * HD) * TT + t;
#pragma unroll
    for (int d = 0; d < 32; d++) cb[(size_t)d * TT] = ctx[d] * inv;
}

// =====================================================================
// Kernel 3: out-proj + residual + LN1.  grid (T/128, B), block 128 (1 thread/token).
// ctx held in 96 registers; W_out broadcast from smem.
// =====================================================================
__global__ __launch_bounds__(128) void k_oproj_ln1(const float* __restrict__ x,
                                                   const float* __restrict__ wo,
                                                   const float* __restrict__ bo,
                                                   const float* __restrict__ g1,
                                                   const float* __restrict__ b1) {
    extern __shared__ float sm[];
    float* Ws = sm;            // [96*96]
    float* As = sm + 96 * 96;  // [96][128]
    __shared__ float Bo[96], G1[96], B1[96];

    int t0 = blockIdx.x * 128;
    int b  = blockIdx.y;
    int tid = threadIdx.x;

    for (int i = tid; i < 96 * 96; i += 128) Ws[i] = wo[i];
    if (tid < 96) { Bo[tid] = bo[tid]; G1[tid] = g1[tid]; B1[tid] = b1[tid]; }

    int t = t0 + tid;
    float cr[96];
    const float* cb = g_ctx + (size_t)b * CC * TT + t;
#pragma unroll
    for (int k = 0; k < 96; k++) cr[k] = cb[(size_t)k * TT];
    __syncthreads();

    const float* xb = x + (size_t)b * CC * TT + t;
    for (int c = 0; c < 96; c += 2) {
        float a00 = 0.f, a01 = 0.f, a10 = 0.f, a11 = 0.f;
#pragma unroll
        for (int k = 0; k < 96; k += 2) {
            a00 += Ws[c * 96 + k] * cr[k];
            a01 += Ws[c * 96 + k + 1] * cr[k + 1];
            a10 += Ws[(c + 1) * 96 + k] * cr[k];
            a11 += Ws[(c + 1) * 96 + k + 1] * cr[k + 1];
        }
        As[c * 128 + tid]       = a00 + a01 + Bo[c]     + xb[(size_t)c * TT];
        As[(c + 1) * 128 + tid] = a10 + a11 + Bo[c + 1] + xb[(size_t)(c + 1) * TT];
    }
    // each thread owns its token column -> no sync needed
    float mu = 0.f;
#pragma unroll
    for (int c = 0; c < 96; c++) mu += As[c * 128 + tid];
    mu *= (1.f / 96.f);
    float var = 0.f;
#pragma unroll
    for (int c = 0; c < 96; c++) {
        float d = As[c * 128 + tid] - mu;
        var += d * d;
    }
    var *= (1.f / 96.f);
    float rs = rsqrtf(var + EPSL);
    float* hb = g_h1 + (size_t)b * CC * TT + t;
    for (int c = 0; c < 96; c++)
        hb[(size_t)c * TT] = (As[c * 128 + tid] - mu) * rs * G1[c] + B1[c];
}

// =====================================================================
// Kernel 4: fused FF1 + ReLU + FF2 + residual + LN2 + LNf + output.
// grid (T/64, B), block 256.  Tile: 64 tokens, full D_FF in chunks of 32.
// Thread map: tx = tid&15 (4 tokens each, float4), ty = tid>>4.
//  u-phase: rows ty, ty+16 of the chunk.  y-phase: c = ty + 16*i, i<6.
// =====================================================================
__global__ __launch_bounds__(256) void k_ff(const float* __restrict__ w1,
                                            const float* __restrict__ b1f,
                                            const float* __restrict__ w2,
                                            const float* __restrict__ b2f,
                                            const float* __restrict__ g2,
                                            const float* __restrict__ b2,
                                            const float* __restrict__ gf,
                                            const float* __restrict__ bf,
                                            float* __restrict__ out) {
    extern __shared__ float sm[];
    float* Hs  = sm;              // [96][64]
    float* Us  = Hs + 96 * 64;    // [32][64]
    float* W1s = Us + 32 * 64;    // [32][100] padded
    float* W2s = W1s + 32 * 100;  // [32][100] padded
    __shared__ float B2F[96], G2[96], B2[96], GF[96], BF[96];

    int t0 = blockIdx.x * 64;
    int b  = blockIdx.y;
    int tid = threadIdx.x;
    int tx = tid & 15;
    int ty = tid >> 4;

    const float* hb = g_h1 + (size_t)b * CC * TT + t0;
    for (int i = tid; i < 96 * 64; i += 256) {
        int c = i >> 6, t = i & 63;
        Hs[i] = hb[(size_t)c * TT + t];
    }
    if (tid < 96) {
        B2F[tid] = b2f[tid]; G2[tid] = g2[tid]; B2[tid] = b2[tid];
        GF[tid] = gf[tid];   BF[tid] = bf[tid];
    }

    float acc[6][4];
#pragma unroll
    for (int i = 0; i < 6; i++)
#pragma unroll
        for (int j = 0; j < 4; j++) acc[i][j] = 0.f;
    __syncthreads();

    for (int jc = 0; jc < DFF; jc += 32) {
        // load W1 chunk [32][96] (contiguous) and W2 chunk (columns jc..jc+31)
        for (int i = tid; i < 32 * 96; i += 256) {
            int j = i / 96, k = i - j * 96;
            W1s[j * 100 + k] = w1[(size_t)jc * 96 + i];
        }
        for (int i = tid; i < 32 * 96; i += 256) {
            int j = i & 31, k = i >> 5;
            W2s[j * 100 + k] = w2[(size_t)k * DFF + jc + j];
        }
        __syncthreads();

        // ---- u = relu(W1_chunk @ h + b1) ----
        float u0[4], u1[4];
        float bv0 = b1f[jc + ty], bv1 = b1f[jc + ty + 16];
#pragma unroll
        for (int j = 0; j < 4; j++) { u0[j] = bv0; u1[j] = bv1; }
#pragma unroll 16
        for (int k = 0; k < 96; k++) {
            float wa = W1s[ty * 100 + k];
            float wb = W1s[(ty + 16) * 100 + k];
            float4 hv = *reinterpret_cast<const float4*>(&Hs[k * 64 + tx * 4]);
            u0[0] += wa * hv.x; u0[1] += wa * hv.y; u0[2] += wa * hv.z; u0[3] += wa * hv.w;
            u1[0] += wb * hv.x; u1[1] += wb * hv.y; u1[2] += wb * hv.z; u1[3] += wb * hv.w;
        }
#pragma unroll
        for (int j = 0; j < 4; j++) {
            Us[ty * 64 + tx * 4 + j]        = fmaxf(u0[j], 0.f);
            Us[(ty + 16) * 64 + tx * 4 + j] = fmaxf(u1[j], 0.f);
        }
        __syncthreads();

        // ---- y += W2_chunk @ u ----
#pragma unroll
        for (int k = 0; k < 32; k++) {
            float4 uv = *reinterpret_cast<const float4*>(&Us[k * 64 + tx * 4]);
#pragma unroll
            for (int i = 0; i < 6; i++) {
                float wv = W2s[k * 100 + ty + 16 * i];
                acc[i][0] += wv * uv.x; acc[i][1] += wv * uv.y;
                acc[i][2] += wv * uv.z; acc[i][3] += wv * uv.w;
            }
        }
        __syncthreads();
    }

    // residual + b2 into Hs (each (c,t) owned by exactly one thread)
#pragma unroll
    for (int i = 0; i < 6; i++) {
        int c = ty + 16 * i;
#pragma unroll
        for (int j = 0; j < 4; j++) {
            int t = tx * 4 + j;
            Hs[c * 64 + t] += acc[i][j] + B2F[c];
        }
    }
    __syncthreads();

    // LN2 then LNf, one thread per token
    if (tid < 64) {
        float mu = 0.f;
#pragma unroll
        for (int c = 0; c < 96; c++) mu += Hs[c * 64 + tid];
        mu *= (1.f / 96.f);
        float var = 0.f;
#pragma unroll
        for (int c = 0; c < 96; c++) {
            float d = Hs[c * 64 + tid] - mu;
            var += d * d;
        }
        var *= (1.f / 96.f);
        float rs1 = rsqrtf(var + EPSL);

        float m2 = 0.f, s2 = 0.f;
#pragma unroll
        for (int c = 0; c < 96; c++) {
            float z = (Hs[c * 64 + tid] - mu) * rs1 * G2[c] + B2[c];
            Hs[c * 64 + tid] = z;
            m2 += z;
            s2 += z * z;
        }
        m2 *= (1.f / 96.f);
        float var2 = s2 * (1.f / 96.f) - m2 * m2;
        float rs2 = rsqrtf(var2 + EPSL);

        float* ob = out + (size_t)b * CC * TT + t0 + tid;
        for (int c = 0; c < 96; c++)
            ob[(size_t)c * TT] = (Hs[c * 64 + tid] - m2) * rs2 * GF[c] + BF[c];
    }
}

// =====================================================================
extern "C" void kernel_launch(void* const* d_in, const int* in_sizes, int n_in,
                              void* d_out, int out_size) {
    const float* x     = (const float*)d_in[0];
    const float* w_qkv = (const float*)d_in[1];
    const float* b_qkv = (const float*)d_in[2];
    const float* w_out = (const float*)d_in[3];
    const float* b_out = (const float*)d_in[4];
    const float* ln1_g = (const float*)d_in[5];
    const float* ln1_b = (const float*)d_in[6];
    const float* w_ff1 = (const float*)d_in[7];
    const float* b_ff1 = (const float*)d_in[8];
    const float* w_ff2 = (const float*)d_in[9];
    const float* b_ff2 = (const float*)d_in[10];
    const float* ln2_g = (const float*)d_in[11];
    const float* ln2_b = (const float*)d_in[12];
    const float* lnf_g = (const float*)d_in[13];
    const float* lnf_b = (const float*)d_in[14];
    float* out = (float*)d_out;

    const int smem1 = (32 * 96 + 96 * 128) * 4;              // 61440
    const int smem2 = (192 * 33 * 2 + 128 * 65) * 4;         // 83968
    const int smem3 = (96 * 96 + 96 * 128) * 4;              // 86016
    const int smem4 = (96 * 64 + 32 * 64 + 2 * 32 * 100) * 4; // 58368

    cudaFuncSetAttribute(k_qkv,       cudaFuncAttributeMaxDynamicSharedMemorySize, smem1);
    cudaFuncSetAttribute(k_attn,      cudaFuncAttributeMaxDynamicSharedMemorySize, smem2);
    cudaFuncSetAttribute(k_oproj_ln1, cudaFuncAttributeMaxDynamicSharedMemorySize, smem3);
    cudaFuncSetAttribute(k_ff,        cudaFuncAttributeMaxDynamicSharedMemorySize, smem4);

    k_qkv<<<dim3(TT / 128, 9, BB), 256, smem1>>>(x, w_qkv, b_qkv);
    k_attn<<<dim3(TT / 128, NH, BB), 128, smem2>>>();
    k_oproj_ln1<<<dim3(TT / 128, BB), 128, smem3>>>(x, w_out, b_out, ln1_g, ln1_b);
    k_ff<<<dim3(TT / 64, BB), 256, smem4>>>(w_ff1, b_ff1, w_ff2, b_ff2,
                                            ln2_g, ln2_b, lnf_g, lnf_b, out);
}

// round 2
// speedup vs baseline: 3.2237x; 3.2237x over previous
#include <cuda_runtime.h>
#include <math.h>

#define BB   8
#define TT   2048
#define CC   96
#define NH   3
#define HD   32
#define DFF  2048
#define HW   32
#define NKEY 65
#define EPSL 1e-5f

// ---- scratch (device globals; no allocation allowed) ----
__device__ float g_qkv[(size_t)BB * 3 * CC * TT];  // (B, 288, T)
__device__ float g_ctx[(size_t)BB * CC * TT];      // attention context
__device__ float g_h1 [(size_t)BB * CC * TT];      // post-LN1 hidden

// =====================================================================
// tf32 helpers
// =====================================================================
__device__ __forceinline__ unsigned f2tf(float f) {
    unsigned u;
    asm("cvt.rna.tf32.f32 %0, %1;" : "=r"(u) : "f"(f));
    return u;
}
__device__ __forceinline__ float f2tff(float f) {
    return __uint_as_float(f2tf(f));
}
__device__ __forceinline__ void mma8(float* d, const unsigned* a, const unsigned* b) {
    asm("mma.sync.aligned.m16n8k8.row.col.f32.tf32.tf32.f32 "
        "{%0,%1,%2,%3}, {%4,%5,%6,%7}, {%8,%9}, {%0,%1,%2,%3};"
        : "+f"(d[0]), "+f"(d[1]), "+f"(d[2]), "+f"(d[3])
        : "r"(a[0]), "r"(a[1]), "r"(a[2]), "r"(a[3]), "r"(b[0]), "r"(b[1]));
}

// =====================================================================
// Kernel 1: QKV projection (unchanged from R1)
// =====================================================================
__global__ __launch_bounds__(256) void k_qkv(const float* __restrict__ x,
                                             const float* __restrict__ w,
                                             const float* __restrict__ bias) {
    extern __shared__ float sm[];
    float* Ws = sm;            // [32][96]
    float* Xs = sm + 32 * 96;  // [96][128]
    __shared__ float Bs[32];

    int t0 = blockIdx.x * 128;
    int m0 = blockIdx.y * 32;
    int b  = blockIdx.z;
    int tid = threadIdx.x;

    for (int i = tid; i < 32 * 96; i += 256) Ws[i] = w[m0 * 96 + i];
    if (tid < 32) Bs[tid] = bias[m0 + tid];
    const float* xb = x + (size_t)b * CC * TT + t0;
    for (int i = tid; i < 96 * 128; i += 256) {
        int k = i >> 7, t = i & 127;
        Xs[k * 128 + t] = xb[(size_t)k * TT + t];
    }
    __syncthreads();

    int g = tid >> 5;
    int tl = tid & 31;
    float acc[4][4];
#pragma unroll
    for (int i = 0; i < 4; i++)
#pragma unroll
        for (int j = 0; j < 4; j++) acc[i][j] = 0.f;

#pragma unroll 4
    for (int k = 0; k < 96; k++) {
        float wv[4], xv[4];
#pragma unroll
        for (int i = 0; i < 4; i++) wv[i] = Ws[(g + 8 * i) * 96 + k];
#pragma unroll
        for (int j = 0; j < 4; j++) xv[j] = Xs[k * 128 + tl + 32 * j];
#pragma unroll
        for (int i = 0; i < 4; i++)
#pragma unroll
            for (int j = 0; j < 4; j++) acc[i][j] += wv[i] * xv[j];
    }

    float* ob = g_qkv + (size_t)b * 3 * CC * TT + t0;
#pragma unroll
    for (int i = 0; i < 4; i++) {
        int m = m0 + g + 8 * i;
        float bv = Bs[g + 8 * i];
#pragma unroll
        for (int j = 0; j < 4; j++)
            ob[(size_t)m * TT + tl + 32 * j] = acc[i][j] + bv;
    }
}

// =====================================================================
// Kernel 2: banded attention (unchanged from R1)
// =====================================================================
__global__ __launch_bounds__(128) void k_attn() {
    extern __shared__ float sm[];
    float* Ks = sm;              // [192][33]
    float* Vs = Ks + 192 * 33;   // [192][33]
    float* Sc = Vs + 192 * 33;   // [128][65]

    int t0 = blockIdx.x * 128;
    int h  = blockIdx.y;
    int b  = blockIdx.z;
    int tid = threadIdx.x;

    const float* kb = g_qkv + (size_t)b * 3 * CC * TT + (size_t)(CC + h * HD) * TT;
    const float* vb = g_qkv + (size_t)b * 3 * CC * TT + (size_t)(2 * CC + h * HD) * TT;

    for (int r = tid; r < 192; r += 128) {
        int s = t0 - HW + r;
        bool ok = (s >= 0) && (s < TT);
#pragma unroll
        for (int d = 0; d < 32; d++) {
            Ks[r * 33 + d] = ok ? kb[(size_t)d * TT + s] : 0.f;
            Vs[r * 33 + d] = ok ? vb[(size_t)d * TT + s] : 0.f;
        }
    }
    __syncthreads();

    int t = t0 + tid;
    const float* qb = g_qkv + (size_t)b * 3 * CC * TT + (size_t)(h * HD) * TT + t;
    float q[32];
#pragma unroll
    for (int d = 0; d < 32; d++) q[d] = qb[(size_t)d * TT];

    const float scale = 0.17677669529663689f;
    float* scRow = Sc + tid * 65;
    float mx = -1e30f;
    for (int j = 0; j < NKEY; j++) {
        const float* kr = Ks + (tid + j) * 33;
        float a0 = 0.f, a1 = 0.f;
#pragma unroll
        for (int d = 0; d < 32; d += 2) {
            a0 += q[d] * kr[d];
            a1 += q[d + 1] * kr[d + 1];
        }
        float a = (a0 + a1) * scale;
        int s = t - HW + j;
        if (s < 0 || s >= TT) a = -1e30f;
        scRow[j] = a;
        mx = fmaxf(mx, a);
    }
    float sum = 0.f;
    for (int j = 0; j < NKEY; j++) {
        float e = __expf(scRow[j] - mx);
        scRow[j] = e;
        sum += e;
    }
    float inv = 1.f / sum;

    float ctx[32];
#pragma unroll
    for (int d = 0; d < 32; d++) ctx[d] = 0.f;
    for (int j = 0; j < NKEY; j++) {
        float p = scRow[j];
        const float* vr = Vs + (tid + j) * 33;
#pragma unroll
        for (int d = 0; d < 32; d++) ctx[d] += p * vr[d];
    }

    float* cb = g_ctx + (size_t)b * CC * TT + (size_t)(h * HD) * TT + t;
#pragma unroll
    for (int d = 0; d < 32; d++) cb[(size_t)d * TT] = ctx[d] * inv;
}

// =====================================================================
// Kernel 3: out-proj + residual + LN1 (unchanged from R1)
// =====================================================================
__global__ __launch_bounds__(128) void k_oproj_ln1(const float* __restrict__ x,
                                                   const float* __restrict__ wo,
                                                   const float* __restrict__ bo,
                                                   const float* __restrict__ g1,
                                                   const float* __restrict__ b1) {
    extern __shared__ float sm[];
    float* Ws = sm;            // [96*96]
    float* As = sm + 96 * 96;  // [96][128]
    __shared__ float Bo[96], G1[96], B1[96];

    int t0 = blockIdx.x * 128;
    int b  = blockIdx.y;
    int tid = threadIdx.x;

    for (int i = tid; i < 96 * 96; i += 128) Ws[i] = wo[i];
    if (tid < 96) { Bo[tid] = bo[tid]; G1[tid] = g1[tid]; B1[tid] = b1[tid]; }

    int t = t0 + tid;
    float cr[96];
    const float* cb = g_ctx + (size_t)b * CC * TT + t;
#pragma unroll
    for (int k = 0; k < 96; k++) cr[k] = cb[(size_t)k * TT];
    __syncthreads();

    const float* xb = x + (size_t)b * CC * TT + t;
    for (int c = 0; c < 96; c += 2) {
        float a00 = 0.f, a01 = 0.f, a10 = 0.f, a11 = 0.f;
#pragma unroll
        for (int k = 0; k < 96; k += 2) {
            a00 += Ws[c * 96 + k] * cr[k];
            a01 += Ws[c * 96 + k + 1] * cr[k + 1];
            a10 += Ws[(c + 1) * 96 + k] * cr[k];
            a11 += Ws[(c + 1) * 96 + k + 1] * cr[k + 1];
        }
        As[c * 128 + tid]       = a00 + a01 + Bo[c]     + xb[(size_t)c * TT];
        As[(c + 1) * 128 + tid] = a10 + a11 + Bo[c + 1] + xb[(size_t)(c + 1) * TT];
    }
    float mu = 0.f;
#pragma unroll
    for (int c = 0; c < 96; c++) mu += As[c * 128 + tid];
    mu *= (1.f / 96.f);
    float var = 0.f;
#pragma unroll
    for (int c = 0; c < 96; c++) {
        float d = As[c * 128 + tid] - mu;
        var += d * d;
    }
    var *= (1.f / 96.f);
    float rs = rsqrtf(var + EPSL);
    float* hb = g_h1 + (size_t)b * CC * TT + t;
    for (int c = 0; c < 96; c++)
        hb[(size_t)c * TT] = (As[c * 128 + tid] - mu) * rs * G1[c] + B1[c];
}

// =====================================================================
// Kernel 4 (REWRITTEN): FF via tf32 tensor-core mma.sync.
// grid (T/128, B) = (16,8) = 128 blocks, one wave. 256 thr = 8 warps.
// Per chunk (JC=64 ff rows): U = relu(W1c @ H) [64x128] via MMA,
// then Y[96][128] += W2c @ U via MMA. Epilogue: +b2+resid, LN2, LNf.
// smem strides: 136 (=8 mod 32), 100/68 (=4 mod 32) -> conflict-free frags.
// =====================================================================
#define HS_STR 136
#define W1_STR 100
#define W2_STR 68

__global__ __launch_bounds__(256, 1) void k_ff(const float* __restrict__ w1,
                                               const float* __restrict__ b1f,
                                               const float* __restrict__ w2,
                                               const float* __restrict__ b2f,
                                               const float* __restrict__ g2,
                                               const float* __restrict__ b2,
                                               const float* __restrict__ gf,
                                               const float* __restrict__ bf,
                                               float* __restrict__ out) {
    extern __shared__ float sm[];
    float* Hs  = sm;                       // [96][136]  tf32 values of h1
    float* Us  = Hs + 96 * HS_STR;         // [64][136]  tf32 relu(ff1)
    float* W1c = Us + 64 * HS_STR;         // [64][100]
    float* W2c = W1c + 64 * W1_STR;        // [96][68]
    __shared__ float B2F[96], G2S[96], B2S[96], GFS[96], BFS[96];

    int t0 = blockIdx.x * 128;
    int b  = blockIdx.y;
    int tid  = threadIdx.x;
    int lane = tid & 31;
    int w    = tid >> 5;
    int gid  = lane >> 2;   // 0..7
    int tig  = lane & 3;    // 0..3

    // u-phase warp tile: M=32 (rows of chunk), N=32 (tokens)
    int m0u = (w & 1) * 32;
    int n0u = (w >> 1) * 32;
    // y-phase warp tile: M=48 (features), N=32 (tokens)
    int m0y = (w & 1) * 48;
    int n0y = (w >> 1) * 32;

    // load H tile (tf32-rounded)
    const float* hb = g_h1 + (size_t)b * CC * TT + t0;
    for (int i = tid; i < 96 * 128; i += 256) {
        int k = i >> 7, t = i & 127;
        Hs[k * HS_STR + t] = f2tff(hb[(size_t)k * TT + t]);
    }
    if (tid < 96) {
        B2F[tid] = b2f[tid]; G2S[tid] = g2[tid]; B2S[tid] = b2[tid];
        GFS[tid] = gf[tid];  BFS[tid] = bf[tid];
    }

    float Y[3][4][4];
#pragma unroll
    for (int i = 0; i < 3; i++)
#pragma unroll
        for (int j = 0; j < 4; j++)
#pragma unroll
            for (int r = 0; r < 4; r++) Y[i][j][r] = 0.f;

    for (int jc = 0; jc < DFF; jc += 64) {
        __syncthreads();  // Hs ready / prev-chunk Us,W2c consumers done
        // load W1 chunk [64][96], W2 chunk [96][64] (tf32-rounded)
        for (int i = tid; i < 64 * 96; i += 256) {
            int r = i / 96, k = i - r * 96;
            W1c[r * W1_STR + k] = f2tff(w1[(size_t)(jc + r) * 96 + k]);
        }
        for (int i = tid; i < 96 * 64; i += 256) {
            int c = i >> 6, kk = i & 63;
            W2c[c * W2_STR + kk] = f2tff(w2[(size_t)c * DFF + jc + kk]);
        }
        __syncthreads();

        // ---- u-phase: U[64][128] = relu(W1c @ Hs + b1) ----
        float ua[2][4][4];
#pragma unroll
        for (int i = 0; i < 2; i++)
#pragma unroll
            for (int j = 0; j < 4; j++)
#pragma unroll
                for (int r = 0; r < 4; r++) ua[i][j][r] = 0.f;

#pragma unroll
        for (int ks = 0; ks < 12; ks++) {
            int k0 = ks * 8;
            unsigned A[2][4], Bv[4][2];
#pragma unroll
            for (int i = 0; i < 2; i++) {
                int r = m0u + 16 * i;
                A[i][0] = __float_as_uint(W1c[(r + gid) * W1_STR + k0 + tig]);
                A[i][1] = __float_as_uint(W1c[(r + gid + 8) * W1_STR + k0 + tig]);
                A[i][2] = __float_as_uint(W1c[(r + gid) * W1_STR + k0 + tig + 4]);
                A[i][3] = __float_as_uint(W1c[(r + gid + 8) * W1_STR + k0 + tig + 4]);
            }
#pragma unroll
            for (int j = 0; j < 4; j++) {
                int col = n0u + 8 * j + gid;
                Bv[j][0] = __float_as_uint(Hs[(k0 + tig) * HS_STR + col]);
                Bv[j][1] = __float_as_uint(Hs[(k0 + tig + 4) * HS_STR + col]);
            }
#pragma unroll
            for (int i = 0; i < 2; i++)
#pragma unroll
                for (int j = 0; j < 4; j++) mma8(ua[i][j], A[i], Bv[j]);
        }

        // bias + relu + store U (tf32) as float2 pairs
#pragma unroll
        for (int i = 0; i < 2; i++) {
            float bvLo = b1f[jc + m0u + 16 * i + gid];
            float bvHi = b1f[jc + m0u + 16 * i + gid + 8];
            int rr = m0u + 16 * i + gid;
#pragma unroll
            for (int j = 0; j < 4; j++) {
                int cc = n0u + 8 * j + 2 * tig;
                float2 lo, hi;
                lo.x = f2tff(fmaxf(ua[i][j][0] + bvLo, 0.f));
                lo.y = f2tff(fmaxf(ua[i][j][1] + bvLo, 0.f));
                hi.x = f2tff(fmaxf(ua[i][j][2] + bvHi, 0.f));
                hi.y = f2tff(fmaxf(ua[i][j][3] + bvHi, 0.f));
                *reinterpret_cast<float2*>(&Us[rr * HS_STR + cc]) = lo;
                *reinterpret_cast<float2*>(&Us[(rr + 8) * HS_STR + cc]) = hi;
            }
        }
        __syncthreads();

        // ---- y-phase: Y += W2c @ U ----
#pragma unroll
        for (int ks = 0; ks < 8; ks++) {
            int k0 = ks * 8;
            unsigned A[3][4], Bv[4][2];
#pragma unroll
            for (int i = 0; i < 3; i++) {
                int r = m0y + 16 * i;
                A[i][0] = __float_as_uint(W2c[(r + gid) * W2_STR + k0 + tig]);
                A[i][1] = __float_as_uint(W2c[(r + gid + 8) * W2_STR + k0 + tig]);
                A[i][2] = __float_as_uint(W2c[(r + gid) * W2_STR + k0 + tig + 4]);
                A[i][3] = __float_as_uint(W2c[(r + gid + 8) * W2_STR + k0 + tig + 4]);
            }
#pragma unroll
            for (int j = 0; j < 4; j++) {
                int col = n0y + 8 * j + gid;
                Bv[j][0] = __float_as_uint(Us[(k0 + tig) * HS_STR + col]);
                Bv[j][1] = __float_as_uint(Us[(k0 + tig + 4) * HS_STR + col]);
            }
#pragma unroll
            for (int i = 0; i < 3; i++)
#pragma unroll
                for (int j = 0; j < 4; j++) mma8(Y[i][j], A[i], Bv[j]);
        }
    }

    // write Y fragments into Hs (fp32), then per-token LN2 + LNf
#pragma unroll
    for (int i = 0; i < 3; i++) {
        int rr = m0y + 16 * i + gid;
#pragma unroll
        for (int j = 0; j < 4; j++) {
            int cc = n0y + 8 * j + 2 * tig;
            float2 lo, hi;
            lo.x = Y[i][j][0]; lo.y = Y[i][j][1];
            hi.x = Y[i][j][2]; hi.y = Y[i][j][3];
            *reinterpret_cast<float2*>(&Hs[rr * HS_STR + cc]) = lo;
            *reinterpret_cast<float2*>(&Hs[(rr + 8) * HS_STR + cc]) = hi;
        }
    }
    __syncthreads();

    if (tid < 128) {
        int t = tid;
        const float* h1p = g_h1 + (size_t)b * CC * TT + t0 + t;
        float mu = 0.f;
#pragma unroll
        for (int c = 0; c < 96; c++) {
            float v = Hs[c * HS_STR + t] + h1p[(size_t)c * TT] + B2F[c];
            Hs[c * HS_STR + t] = v;
            mu += v;
        }
        mu *= (1.f / 96.f);
        float var = 0.f;
#pragma unroll
        for (int c = 0; c < 96; c++) {
            float d = Hs[c * HS_STR + t] - mu;
            var += d * d;
        }
        var *= (1.f / 96.f);
        float rs1 = rsqrtf(var + EPSL);

        float m2 = 0.f, s2 = 0.f;
#pragma unroll
        for (int c = 0; c < 96; c++) {
            float z = (Hs[c * HS_STR + t] - mu) * rs1 * G2S[c] + B2S[c];
            Hs[c * HS_STR + t] = z;
            m2 += z;
            s2 += z * z;
        }
        m2 *= (1.f / 96.f);
        float var2 = s2 * (1.f / 96.f) - m2 * m2;
        float rs2 = rsqrtf(var2 + EPSL);

        float* ob = out + (size_t)b * CC * TT + t0 + t;
        for (int c = 0; c < 96; c++)
            ob[(size_t)c * TT] = (Hs[c * HS_STR + t] - m2) * rs2 * GFS[c] + BFS[c];
    }
}

// =====================================================================
extern "C" void kernel_launch(void* const* d_in, const int* in_sizes, int n_in,
                              void* d_out, int out_size) {
    const float* x     = (const float*)d_in[0];
    const float* w_qkv = (const float*)d_in[1];
    const float* b_qkv = (const float*)d_in[2];
    const float* w_out = (const float*)d_in[3];
    const float* b_out = (const float*)d_in[4];
    const float* ln1_g = (const float*)d_in[5];
    const float* ln1_b = (const float*)d_in[6];
    const float* w_ff1 = (const float*)d_in[7];
    const float* b_ff1 = (const float*)d_in[8];
    const float* w_ff2 = (const float*)d_in[9];
    const float* b_ff2 = (const float*)d_in[10];
    const float* ln2_g = (const float*)d_in[11];
    const float* ln2_b = (const float*)d_in[12];
    const float* lnf_g = (const float*)d_in[13];
    const float* lnf_b = (const float*)d_in[14];
    float* out = (float*)d_out;

    const int smem1 = (32 * 96 + 96 * 128) * 4;
    const int smem2 = (192 * 33 * 2 + 128 * 65) * 4;
    const int smem3 = (96 * 96 + 96 * 128) * 4;
    const int smem4 = (96 * HS_STR + 64 * HS_STR + 64 * W1_STR + 96 * W2_STR) * 4;  // 138752

    cudaFuncSetAttribute(k_qkv,       cudaFuncAttributeMaxDynamicSharedMemorySize, smem1);
    cudaFuncSetAttribute(k_attn,      cudaFuncAttributeMaxDynamicSharedMemorySize, smem2);
    cudaFuncSetAttribute(k_oproj_ln1, cudaFuncAttributeMaxDynamicSharedMemorySize, smem3);
    cudaFuncSetAttribute(k_ff,        cudaFuncAttributeMaxDynamicSharedMemorySize, smem4);

    k_qkv<<<dim3(TT / 128, 9, BB), 256, smem1>>>(x, w_qkv, b_qkv);
    k_attn<<<dim3(TT / 128, NH, BB), 128, smem2>>>();
    k_oproj_ln1<<<dim3(TT / 128, BB), 128, smem3>>>(x, w_out, b_out, ln1_g, ln1_b);
    k_ff<<<dim3(TT / 128, BB), 256, smem4>>>(w_ff1, b_ff1, w_ff2, b_ff2,
                                             ln2_g, ln2_b, lnf_g, lnf_b, out);
}

// round 3
// speedup vs baseline: 4.5737x; 1.4188x over previous
#include <cuda_runtime.h>
#include <cuda_fp16.h>
#include <math.h>

#define BB   8
#define TT   2048
#define CC   96
#define NH   3
#define HD   32
#define DFF  2048
#define HW   32
#define NKEY 65
#define EPSL 1e-5f

// ---- scratch (device globals; no allocation allowed) ----
__device__ float  g_qkv[(size_t)BB * 3 * CC * TT];  // (B, 288, T)
__device__ float  g_ctx[(size_t)BB * CC * TT];      // attention context
__device__ float  g_h1 [(size_t)BB * CC * TT];      // post-LN1 hidden (fp32, feature-major)
__device__ __half g_h16[(size_t)BB * TT * CC];      // post-LN1 hidden (fp16, token-major)

// =====================================================================
// fp16 mma helper: D(16x8,f32) += A(16x16,f16,row) * B(16x8,f16,col)
// =====================================================================
__device__ __forceinline__ void mma16(float* d, const unsigned* a, const unsigned* b) {
    asm("mma.sync.aligned.m16n8k16.row.col.f32.f16.f16.f32 "
        "{%0,%1,%2,%3}, {%4,%5,%6,%7}, {%8,%9}, {%0,%1,%2,%3};"
        : "+f"(d[0]), "+f"(d[1]), "+f"(d[2]), "+f"(d[3])
        : "r"(a[0]), "r"(a[1]), "r"(a[2]), "r"(a[3]), "r"(b[0]), "r"(b[1]));
}

// =====================================================================
// Kernel 1: QKV projection (unchanged)
// =====================================================================
__global__ __launch_bounds__(256) void k_qkv(const float* __restrict__ x,
                                             const float* __restrict__ w,
                                             const float* __restrict__ bias) {
    extern __shared__ float sm[];
    float* Ws = sm;            // [32][96]
    float* Xs = sm + 32 * 96;  // [96][128]
    __shared__ float Bs[32];

    int t0 = blockIdx.x * 128;
    int m0 = blockIdx.y * 32;
    int b  = blockIdx.z;
    int tid = threadIdx.x;

    for (int i = tid; i < 32 * 96; i += 256) Ws[i] = w[m0 * 96 + i];
    if (tid < 32) Bs[tid] = bias[m0 + tid];
    const float* xb = x + (size_t)b * CC * TT + t0;
    for (int i = tid; i < 96 * 128; i += 256) {
        int k = i >> 7, t = i & 127;
        Xs[k * 128 + t] = xb[(size_t)k * TT + t];
    }
    __syncthreads();

    int g = tid >> 5;
    int tl = tid & 31;
    float acc[4][4];
#pragma unroll
    for (int i = 0; i < 4; i++)
#pragma unroll
        for (int j = 0; j < 4; j++) acc[i][j] = 0.f;

#pragma unroll 4
    for (int k = 0; k < 96; k++) {
        float wv[4], xv[4];
#pragma unroll
        for (int i = 0; i < 4; i++) wv[i] = Ws[(g + 8 * i) * 96 + k];
#pragma unroll
        for (int j = 0; j < 4; j++) xv[j] = Xs[k * 128 + tl + 32 * j];
#pragma unroll
        for (int i = 0; i < 4; i++)
#pragma unroll
            for (int j = 0; j < 4; j++) acc[i][j] += wv[i] * xv[j];
    }

    float* ob = g_qkv + (size_t)b * 3 * CC * TT + t0;
#pragma unroll
    for (int i = 0; i < 4; i++) {
        int m = m0 + g + 8 * i;
        float bv = Bs[g + 8 * i];
#pragma unroll
        for (int j = 0; j < 4; j++)
            ob[(size_t)m * TT + tl + 32 * j] = acc[i][j] + bv;
    }
}

// =====================================================================
// Kernel 2: banded attention (unchanged)
// =====================================================================
__global__ __launch_bounds__(128) void k_attn() {
    extern __shared__ float sm[];
    float* Ks = sm;              // [192][33]
    float* Vs = Ks + 192 * 33;   // [192][33]
    float* Sc = Vs + 192 * 33;   // [128][65]

    int t0 = blockIdx.x * 128;
    int h  = blockIdx.y;
    int b  = blockIdx.z;
    int tid = threadIdx.x;

    const float* kb = g_qkv + (size_t)b * 3 * CC * TT + (size_t)(CC + h * HD) * TT;
    const float* vb = g_qkv + (size_t)b * 3 * CC * TT + (size_t)(2 * CC + h * HD) * TT;

    for (int r = tid; r < 192; r += 128) {
        int s = t0 - HW + r;
        bool ok = (s >= 0) && (s < TT);
#pragma unroll
        for (int d = 0; d < 32; d++) {
            Ks[r * 33 + d] = ok ? kb[(size_t)d * TT + s] : 0.f;
            Vs[r * 33 + d] = ok ? vb[(size_t)d * TT + s] : 0.f;
        }
    }
    __syncthreads();

    int t = t0 + tid;
    const float* qb = g_qkv + (size_t)b * 3 * CC * TT + (size_t)(h * HD) * TT + t;
    float q[32];
#pragma unroll
    for (int d = 0; d < 32; d++) q[d] = qb[(size_t)d * TT];

    const float scale = 0.17677669529663689f;
    float* scRow = Sc + tid * 65;
    float mx = -1e30f;
    for (int j = 0; j < NKEY; j++) {
        const float* kr = Ks + (tid + j) * 33;
        float a0 = 0.f, a1 = 0.f;
#pragma unroll
        for (int d = 0; d < 32; d += 2) {
            a0 += q[d] * kr[d];
            a1 += q[d + 1] * kr[d + 1];
        }
        float a = (a0 + a1) * scale;
        int s = t - HW + j;
        if (s < 0 || s >= TT) a = -1e30f;
        scRow[j] = a;
        mx = fmaxf(mx, a);
    }
    float sum = 0.f;
    for (int j = 0; j < NKEY; j++) {
        float e = __expf(scRow[j] - mx);
        scRow[j] = e;
        sum += e;
    }
    float inv = 1.f / sum;

    float ctx[32];
#pragma unroll
    for (int d = 0; d < 32; d++) ctx[d] = 0.f;
    for (int j = 0; j < NKEY; j++) {
        float p = scRow[j];
        const float* vr = Vs + (tid + j) * 33;
#pragma unroll
        for (int d = 0; d < 32; d++) ctx[d] += p * vr[d];
    }

    float* cb = g_ctx + (size_t)b * CC * TT + (size_t)(h * HD) * TT + t;
#pragma unroll
    for (int d = 0; d < 32; d++) cb[(size_t)d * TT] = ctx[d] * inv;
}

// =====================================================================
// Kernel 3: out-proj + residual + LN1; writes fp32 feature-major AND
// fp16 token-major copies of h1.
// =====================================================================
__global__ __launch_bounds__(128) void k_oproj_ln1(const float* __restrict__ x,
                                                   const float* __restrict__ wo,
                                                   const float* __restrict__ bo,
                                                   const float* __restrict__ g1,
                                                   const float* __restrict__ b1) {
    extern __shared__ float sm[];
    float* Ws = sm;            // [96*96]
    float* As = sm + 96 * 96;  // [96][128]
    __shared__ float Bo[96], G1[96], B1[96];

    int t0 = blockIdx.x * 128;
    int b  = blockIdx.y;
    int tid = threadIdx.x;

    for (int i = tid; i < 96 * 96; i += 128) Ws[i] = wo[i];
    if (tid < 96) { Bo[tid] = bo[tid]; G1[tid] = g1[tid]; B1[tid] = b1[tid]; }

    int t = t0 + tid;
    float cr[96];
    const float* cb = g_ctx + (size_t)b * CC * TT + t;
#pragma unroll
    for (int k = 0; k < 96; k++) cr[k] = cb[(size_t)k * TT];
    __syncthreads();

    const float* xb = x + (size_t)b * CC * TT + t;
    for (int c = 0; c < 96; c += 2) {
        float a00 = 0.f, a01 = 0.f, a10 = 0.f, a11 = 0.f;
#pragma unroll
        for (int k = 0; k < 96; k += 2) {
            a00 += Ws[c * 96 + k] * cr[k];
            a01 += Ws[c * 96 + k + 1] * cr[k + 1];
            a10 += Ws[(c + 1) * 96 + k] * cr[k];
            a11 += Ws[(c + 1) * 96 + k + 1] * cr[k + 1];
        }
        As[c * 128 + tid]       = a00 + a01 + Bo[c]     + xb[(size_t)c * TT];
        As[(c + 1) * 128 + tid] = a10 + a11 + Bo[c + 1] + xb[(size_t)(c + 1) * TT];
    }
    float mu = 0.f;
#pragma unroll
    for (int c = 0; c < 96; c++) mu += As[c * 128 + tid];
    mu *= (1.f / 96.f);
    float var = 0.f;
#pragma unroll
    for (int c = 0; c < 96; c++) {
        float d = As[c * 128 + tid] - mu;
        var += d * d;
    }
    var *= (1.f / 96.f);
    float rs = rsqrtf(var + EPSL);

    float* hb = g_h1 + (size_t)b * CC * TT + t;
    unsigned hu[48];
#pragma unroll
    for (int c = 0; c < 96; c += 2) {
        float v0 = (As[c * 128 + tid] - mu) * rs * G1[c] + B1[c];
        float v1 = (As[(c + 1) * 128 + tid] - mu) * rs * G1[c + 1] + B1[c + 1];
        hb[(size_t)c * TT] = v0;
        hb[(size_t)(c + 1) * TT] = v1;
        __half2 p = __floats2half2_rn(v0, v1);
        hu[c >> 1] = *reinterpret_cast<unsigned*>(&p);
    }
    uint4* dst = (uint4*)(g_h16 + ((size_t)b * TT + t) * 96);
#pragma unroll
    for (int q = 0; q < 12; q++)
        dst[q] = make_uint4(hu[4 * q], hu[4 * q + 1], hu[4 * q + 2], hu[4 * q + 3]);
}

// =====================================================================
// Kernel 4: FF via fp16 m16n8k16 mma, transposed formulation (tokens=M).
// grid (16,8)=128 blocks, 512 threads (16 warps).
//   U^T[128 tok][64 ff] = relu(Hs[128][96] @ W1c^T) per chunk (k=96, 6 ksteps)
//   Y^T[128 tok][96 ft] += Us @ W2c^T                       (k=64, 4 ksteps)
// smem strides (halves): 104 and 72 -> conflict-free quad patterns.
// =====================================================================
#define HS2 104
#define US2 72

__global__ __launch_bounds__(512, 1) void k_ff(const float* __restrict__ w1,
                                               const float* __restrict__ b1f,
                                               const float* __restrict__ w2,
                                               const float* __restrict__ b2f,
                                               const float* __restrict__ g2,
                                               const float* __restrict__ b2,
                                               const float* __restrict__ gf,
                                               const float* __restrict__ bf,
                                               float* __restrict__ out) {
    extern __shared__ char smraw[];
    __half* Hs  = (__half*)smraw;           // [128][104]
    __half* Us  = Hs + 128 * HS2;           // [128][72]
    __half* W1c = Us + 128 * US2;           // [64][104]
    __half* W2c = W1c + 64 * HS2;           // [96][72]
    __shared__ float B2F[96], G2S[96], B2S[96], GFS[96], BFS[96];

    int t0 = blockIdx.x * 128;
    int b  = blockIdx.y;
    int tid  = threadIdx.x;
    int lane = tid & 31;
    int w    = tid >> 5;
    int gid  = lane >> 2;
    int tig  = lane & 3;

    int m0u = (w & 3) * 32;    // tokens (u-phase)
    int n0u = (w >> 2) * 16;   // ff cols
    int m0y = (w & 3) * 32;    // tokens (y-phase)
    int n0y = (w >> 2) * 24;   // feature cols

    // load Hs: 128 tokens x 96 halves, vectorized
    const uint4* hsrc = (const uint4*)(g_h16 + ((size_t)b * TT + t0) * 96);
    for (int i = tid; i < 128 * 12; i += 512) {
        int tok = i / 12, seg = i - tok * 12;
        *(uint4*)(Hs + tok * HS2 + seg * 8) = hsrc[i];
    }
    if (tid < 96) {
        B2F[tid] = b2f[tid]; G2S[tid] = g2[tid]; B2S[tid] = b2[tid];
        GFS[tid] = gf[tid];  BFS[tid] = bf[tid];
    }

    float Y[2][3][4];
#pragma unroll
    for (int i = 0; i < 2; i++)
#pragma unroll
        for (int j = 0; j < 3; j++)
#pragma unroll
            for (int r = 0; r < 4; r++) Y[i][j][r] = 0.f;

    for (int jc = 0; jc < DFF; jc += 64) {
        __syncthreads();  // prev y-phase done (W2c reusable); Hs ready on iter 0
        // stage W1 chunk [64][96] and W2 chunk [96][64] as fp16
        for (int i = tid; i < 64 * 24; i += 512) {
            int r = i / 24, q = i - r * 24;
            float4 v = *(const float4*)(w1 + (size_t)(jc + r) * 96 + 4 * q);
            __half2 p0 = __floats2half2_rn(v.x, v.y);
            __half2 p1 = __floats2half2_rn(v.z, v.w);
            *(__half2*)(W1c + r * HS2 + 4 * q)     = p0;
            *(__half2*)(W1c + r * HS2 + 4 * q + 2) = p1;
        }
        for (int i = tid; i < 96 * 16; i += 512) {
            int c = i / 16, q = i - c * 16;
            float4 v = *(const float4*)(w2 + (size_t)c * DFF + jc + 4 * q);
            __half2 p0 = __floats2half2_rn(v.x, v.y);
            __half2 p1 = __floats2half2_rn(v.z, v.w);
            *(__half2*)(W2c + c * US2 + 4 * q)     = p0;
            *(__half2*)(W2c + c * US2 + 4 * q + 2) = p1;
        }
        __syncthreads();

        // ---- u-phase: ua = Hs(tile) @ W1c(tile)^T ----
        float ua[2][2][4];
#pragma unroll
        for (int i = 0; i < 2; i++)
#pragma unroll
            for (int j = 0; j < 2; j++)
#pragma unroll
                for (int r = 0; r < 4; r++) ua[i][j][r] = 0.f;

#pragma unroll
        for (int ks = 0; ks < 6; ks++) {
            int k0 = ks * 16;
            unsigned A[2][4], Bv[2][2];
#pragma unroll
            for (int i = 0; i < 2; i++) {
                const __half* base = Hs + (m0u + 16 * i + gid) * HS2 + k0 + 2 * tig;
                A[i][0] = *(const unsigned*)(base);
                A[i][1] = *(const unsigned*)(base + 8 * HS2);
                A[i][2] = *(const unsigned*)(base + 8);
                A[i][3] = *(const unsigned*)(base + 8 * HS2 + 8);
            }
#pragma unroll
            for (int j = 0; j < 2; j++) {
                const __half* bb = W1c + (n0u + 8 * j + gid) * HS2 + k0 + 2 * tig;
                Bv[j][0] = *(const unsigned*)(bb);
                Bv[j][1] = *(const unsigned*)(bb + 8);
            }
#pragma unroll
            for (int i = 0; i < 2; i++)
#pragma unroll
                for (int j = 0; j < 2; j++) mma16(ua[i][j], A[i], Bv[j]);
        }

        // bias + relu + store U (fp16, token-major)
#pragma unroll
        for (int j = 0; j < 2; j++) {
            float2 bv = *(const float2*)(b1f + jc + n0u + 8 * j + 2 * tig);
#pragma unroll
            for (int i = 0; i < 2; i++) {
                __half2 lo = __floats2half2_rn(fmaxf(ua[i][j][0] + bv.x, 0.f),
                                               fmaxf(ua[i][j][1] + bv.y, 0.f));
                __half2 hi = __floats2half2_rn(fmaxf(ua[i][j][2] + bv.x, 0.f),
                                               fmaxf(ua[i][j][3] + bv.y, 0.f));
                *(__half2*)(Us + (m0u + 16 * i + gid) * US2 + n0u + 8 * j + 2 * tig)     = lo;
                *(__half2*)(Us + (m0u + 16 * i + gid + 8) * US2 + n0u + 8 * j + 2 * tig) = hi;
            }
        }
        __syncthreads();

        // ---- y-phase: Y += Us(tile) @ W2c(tile)^T ----
#pragma unroll
        for (int ks = 0; ks < 4; ks++) {
            int k0 = ks * 16;
            unsigned A[2][4], Bv[3][2];
#pragma unroll
            for (int i = 0; i < 2; i++) {
                const __half* base = Us + (m0y + 16 * i + gid) * US2 + k0 + 2 * tig;
                A[i][0] = *(const unsigned*)(base);
                A[i][1] = *(const unsigned*)(base + 8 * US2);
                A[i][2] = *(const unsigned*)(base + 8);
                A[i][3] = *(const unsigned*)(base + 8 * US2 + 8);
            }
#pragma unroll
            for (int j = 0; j < 3; j++) {
                const __half* bb = W2c + (n0y + 8 * j + gid) * US2 + k0 + 2 * tig;
                Bv[j][0] = *(const unsigned*)(bb);
                Bv[j][1] = *(const unsigned*)(bb + 8);
            }
#pragma unroll
            for (int i = 0; i < 2; i++)
#pragma unroll
                for (int j = 0; j < 3; j++) mma16(Y[i][j], A[i], Bv[j]);
        }
    }

    // dump Y^T to smem fp32 [128 tok][101], then LN2+LNf per token
    __syncthreads();
    float* Ys = (float*)smraw;  // aliases compute buffers (all dead now)
#pragma unroll
    for (int i = 0; i < 2; i++)
#pragma unroll
        for (int j = 0; j < 3; j++) {
            int row = m0y + 16 * i + gid;
            int col = n0y + 8 * j + 2 * tig;
            Ys[row * 101 + col]           = Y[i][j][0];
            Ys[row * 101 + col + 1]       = Y[i][j][1];
            Ys[(row + 8) * 101 + col]     = Y[i][j][2];
            Ys[(row + 8) * 101 + col + 1] = Y[i][j][3];
        }
    __syncthreads();

    if (tid < 128) {
        int t = tid;
        const float* h1p = g_h1 + (size_t)b * CC * TT + t0 + t;
        float* yr = Ys + t * 101;
        float mu = 0.f;
#pragma unroll
        for (int c = 0; c < 96; c++) {
            float v = yr[c] + h1p[(size_t)c * TT] + B2F[c];
            yr[c] = v;
            mu += v;
        }
        mu *= (1.f / 96.f);
        float var = 0.f;
#pragma unroll
        for (int c = 0; c < 96; c++) {
            float d = yr[c] - mu;
            var += d * d;
        }
        var *= (1.f / 96.f);
        float rs1 = rsqrtf(var + EPSL);

        float m2 = 0.f, s2 = 0.f;
#pragma unroll
        for (int c = 0; c < 96; c++) {
            float z = (yr[c] - mu) * rs1 * G2S[c] + B2S[c];
            yr[c] = z;
            m2 += z;
            s2 += z * z;
        }
        m2 *= (1.f / 96.f);
        float var2 = s2 * (1.f / 96.f) - m2 * m2;
        float rs2 = rsqrtf(var2 + EPSL);

        float* ob = out + (size_t)b * CC * TT + t0 + t;
        for (int c = 0; c < 96; c++)
            ob[(size_t)c * TT] = (yr[c] - m2) * rs2 * GFS[c] + BFS[c];
    }
}

// =====================================================================
extern "C" void kernel_launch(void* const* d_in, const int* in_sizes, int n_in,
                              void* d_out, int out_size) {
    const float* x     = (const float*)d_in[0];
    const float* w_qkv = (const float*)d_in[1];
    const float* b_qkv = (const float*)d_in[2];
    const float* w_out = (const float*)d_in[3];
    const float* b_out = (const float*)d_in[4];
    const float* ln1_g = (const float*)d_in[5];
    const float* ln1_b = (const float*)d_in[6];
    const float* w_ff1 = (const float*)d_in[7];
    const float* b_ff1 = (const float*)d_in[8];
    const float* w_ff2 = (const float*)d_in[9];
    const float* b_ff2 = (const float*)d_in[10];
    const float* ln2_g = (const float*)d_in[11];
    const float* ln2_b = (const float*)d_in[12];
    const float* lnf_g = (const float*)d_in[13];
    const float* lnf_b = (const float*)d_in[14];
    float* out = (float*)d_out;

    const int smem1 = (32 * 96 + 96 * 128) * 4;
    const int smem2 = (192 * 33 * 2 + 128 * 65) * 4;
    const int smem3 = (96 * 96 + 96 * 128) * 4;
    const int smem4 = (128 * HS2 + 128 * US2 + 64 * HS2 + 96 * US2) * 2;  // 72192 B

    cudaFuncSetAttribute(k_qkv,       cudaFuncAttributeMaxDynamicSharedMemorySize, smem1);
    cudaFuncSetAttribute(k_attn,      cudaFuncAttributeMaxDynamicSharedMemorySize, smem2);
    cudaFuncSetAttribute(k_oproj_ln1, cudaFuncAttributeMaxDynamicSharedMemorySize, smem3);
    cudaFuncSetAttribute(k_ff,        cudaFuncAttributeMaxDynamicSharedMemorySize, smem4);

    k_qkv<<<dim3(TT / 128, 9, BB), 256, smem1>>>(x, w_qkv, b_qkv);
    k_attn<<<dim3(TT / 128, NH, BB), 128, smem2>>>();
    k_oproj_ln1<<<dim3(TT / 128, BB), 128, smem3>>>(x, w_out, b_out, ln1_g, ln1_b);
    k_ff<<<dim3(TT / 128, BB), 512, smem4>>>(w_ff1, b_ff1, w_ff2, b_ff2,
                                             ln2_g, ln2_b, lnf_g, lnf_b, out);
}

// round 4
// speedup vs baseline: 5.2537x; 1.1487x over previous
#include <cuda_runtime.h>
#include <cuda_fp16.h>
#include <math.h>

#define BB   8
#define TT   2048
#define CC   96
#define NH   3
#define HD   32
#define DFF  2048
#define HW   32
#define NKEY 65
#define EPSL 1e-5f

// ---- scratch (device globals; no allocation allowed) ----
__device__ float  g_qkv[(size_t)BB * 3 * CC * TT];
__device__ float  g_ctx[(size_t)BB * CC * TT];
__device__ float  g_h1 [(size_t)BB * CC * TT];      // post-LN1 (fp32, feature-major)
__device__ __half g_h16[(size_t)BB * TT * CC];      // post-LN1 (fp16, token-major)
__device__ __half g_w1h[(size_t)DFF * CC];          // fp16 W1
__device__ __half g_w2h[(size_t)CC * DFF];          // fp16 W2

// =====================================================================
__device__ __forceinline__ void mma16(float* d, const unsigned* a, const unsigned* b) {
    asm("mma.sync.aligned.m16n8k16.row.col.f32.f16.f16.f32 "
        "{%0,%1,%2,%3}, {%4,%5,%6,%7}, {%8,%9}, {%0,%1,%2,%3};"
        : "+f"(d[0]), "+f"(d[1]), "+f"(d[2]), "+f"(d[3])
        : "r"(a[0]), "r"(a[1]), "r"(a[2]), "r"(a[3]), "r"(b[0]), "r"(b[1]));
}
__device__ __forceinline__ void cpa16(void* dst, const void* src) {
    unsigned d = (unsigned)__cvta_generic_to_shared(dst);
    asm volatile("cp.async.cg.shared.global [%0], [%1], 16;" :: "r"(d), "l"(src));
}
__device__ __forceinline__ void cpa_commit() {
    asm volatile("cp.async.commit_group;" ::: "memory");
}
__device__ __forceinline__ void cpa_wait_all() {
    asm volatile("cp.async.wait_group 0;" ::: "memory");
}

// =====================================================================
// Kernel 0: weight prep (fp32 -> fp16)
// =====================================================================
__global__ __launch_bounds__(256) void k_prep(const float* __restrict__ w1,
                                              const float* __restrict__ w2) {
    int i = blockIdx.x * 256 + threadIdx.x;
    const int N = DFF * CC;  // 196608
    if (i < N) {
        g_w1h[i] = __float2half_rn(w1[i]);
        g_w2h[i] = __float2half_rn(w2[i]);
    }
}

// =====================================================================
// Kernel 1: QKV projection (unchanged)
// =====================================================================
__global__ __launch_bounds__(256) void k_qkv(const float* __restrict__ x,
                                             const float* __restrict__ w,
                                             const float* __restrict__ bias) {
    extern __shared__ float sm[];
    float* Ws = sm;            // [32][96]
    float* Xs = sm + 32 * 96;  // [96][128]
    __shared__ float Bs[32];

    int t0 = blockIdx.x * 128;
    int m0 = blockIdx.y * 32;
    int b  = blockIdx.z;
    int tid = threadIdx.x;

    for (int i = tid; i < 32 * 96; i += 256) Ws[i] = w[m0 * 96 + i];
    if (tid < 32) Bs[tid] = bias[m0 + tid];
    const float* xb = x + (size_t)b * CC * TT + t0;
    for (int i = tid; i < 96 * 128; i += 256) {
        int k = i >> 7, t = i & 127;
        Xs[k * 128 + t] = xb[(size_t)k * TT + t];
    }
    __syncthreads();

    int g = tid >> 5;
    int tl = tid & 31;
    float acc[4][4];
#pragma unroll
    for (int i = 0; i < 4; i++)
#pragma unroll
        for (int j = 0; j < 4; j++) acc[i][j] = 0.f;

#pragma unroll 4
    for (int k = 0; k < 96; k++) {
        float wv[4], xv[4];
#pragma unroll
        for (int i = 0; i < 4; i++) wv[i] = Ws[(g + 8 * i) * 96 + k];
#pragma unroll
        for (int j = 0; j < 4; j++) xv[j] = Xs[k * 128 + tl + 32 * j];
#pragma unroll
        for (int i = 0; i < 4; i++)
#pragma unroll
            for (int j = 0; j < 4; j++) acc[i][j] += wv[i] * xv[j];
    }

    float* ob = g_qkv + (size_t)b * 3 * CC * TT + t0;
#pragma unroll
    for (int i = 0; i < 4; i++) {
        int m = m0 + g + 8 * i;
        float bv = Bs[g + 8 * i];
#pragma unroll
        for (int j = 0; j < 4; j++)
            ob[(size_t)m * TT + tl + 32 * j] = acc[i][j] + bv;
    }
}

// =====================================================================
// Kernel 2: banded attention (unchanged)
// =====================================================================
__global__ __launch_bounds__(128) void k_attn() {
    extern __shared__ float sm[];
    float* Ks = sm;              // [192][33]
    float* Vs = Ks + 192 * 33;   // [192][33]
    float* Sc = Vs + 192 * 33;   // [128][65]

    int t0 = blockIdx.x * 128;
    int h  = blockIdx.y;
    int b  = blockIdx.z;
    int tid = threadIdx.x;

    const float* kb = g_qkv + (size_t)b * 3 * CC * TT + (size_t)(CC + h * HD) * TT;
    const float* vb = g_qkv + (size_t)b * 3 * CC * TT + (size_t)(2 * CC + h * HD) * TT;

    for (int r = tid; r < 192; r += 128) {
        int s = t0 - HW + r;
        bool ok = (s >= 0) && (s < TT);
#pragma unroll
        for (int d = 0; d < 32; d++) {
            Ks[r * 33 + d] = ok ? kb[(size_t)d * TT + s] : 0.f;
            Vs[r * 33 + d] = ok ? vb[(size_t)d * TT + s] : 0.f;
        }
    }
    __syncthreads();

    int t = t0 + tid;
    const float* qb = g_qkv + (size_t)b * 3 * CC * TT + (size_t)(h * HD) * TT + t;
    float q[32];
#pragma unroll
    for (int d = 0; d < 32; d++) q[d] = qb[(size_t)d * TT];

    const float scale = 0.17677669529663689f;
    float* scRow = Sc + tid * 65;
    float mx = -1e30f;
    for (int j = 0; j < NKEY; j++) {
        const float* kr = Ks + (tid + j) * 33;
        float a0 = 0.f, a1 = 0.f;
#pragma unroll
        for (int d = 0; d < 32; d += 2) {
            a0 += q[d] * kr[d];
            a1 += q[d + 1] * kr[d + 1];
        }
        float a = (a0 + a1) * scale;
        int s = t - HW + j;
        if (s < 0 || s >= TT) a = -1e30f;
        scRow[j] = a;
        mx = fmaxf(mx, a);
    }
    float sum = 0.f;
    for (int j = 0; j < NKEY; j++) {
        float e = __expf(scRow[j] - mx);
        scRow[j] = e;
        sum += e;
    }
    float inv = 1.f / sum;

    float ctx[32];
#pragma unroll
    for (int d = 0; d < 32; d++) ctx[d] = 0.f;
    for (int j = 0; j < NKEY; j++) {
        float p = scRow[j];
        const float* vr = Vs + (tid + j) * 33;
#pragma unroll
        for (int d = 0; d < 32; d++) ctx[d] += p * vr[d];
    }

    float* cb = g_ctx + (size_t)b * CC * TT + (size_t)(h * HD) * TT + t;
#pragma unroll
    for (int d = 0; d < 32; d++) cb[(size_t)d * TT] = ctx[d] * inv;
}

// =====================================================================
// Kernel 3: out-proj + residual + LN1 (unchanged)
// =====================================================================
__global__ __launch_bounds__(128) void k_oproj_ln1(const float* __restrict__ x,
                                                   const float* __restrict__ wo,
                                                   const float* __restrict__ bo,
                                                   const float* __restrict__ g1,
                                                   const float* __restrict__ b1) {
    extern __shared__ float sm[];
    float* Ws = sm;            // [96*96]
    float* As = sm + 96 * 96;  // [96][128]
    __shared__ float Bo[96], G1[96], B1[96];

    int t0 = blockIdx.x * 128;
    int b  = blockIdx.y;
    int tid = threadIdx.x;

    for (int i = tid; i < 96 * 96; i += 128) Ws[i] = wo[i];
    if (tid < 96) { Bo[tid] = bo[tid]; G1[tid] = g1[tid]; B1[tid] = b1[tid]; }

    int t = t0 + tid;
    float cr[96];
    const float* cb = g_ctx + (size_t)b * CC * TT + t;
#pragma unroll
    for (int k = 0; k < 96; k++) cr[k] = cb[(size_t)k * TT];
    __syncthreads();

    const float* xb = x + (size_t)b * CC * TT + t;
    for (int c = 0; c < 96; c += 2) {
        float a00 = 0.f, a01 = 0.f, a10 = 0.f, a11 = 0.f;
#pragma unroll
        for (int k = 0; k < 96; k += 2) {
            a00 += Ws[c * 96 + k] * cr[k];
            a01 += Ws[c * 96 + k + 1] * cr[k + 1];
            a10 += Ws[(c + 1) * 96 + k] * cr[k];
            a11 += Ws[(c + 1) * 96 + k + 1] * cr[k + 1];
        }
        As[c * 128 + tid]       = a00 + a01 + Bo[c]     + xb[(size_t)c * TT];
        As[(c + 1) * 128 + tid] = a10 + a11 + Bo[c + 1] + xb[(size_t)(c + 1) * TT];
    }
    float mu = 0.f;
#pragma unroll
    for (int c = 0; c < 96; c++) mu += As[c * 128 + tid];
    mu *= (1.f / 96.f);
    float var = 0.f;
#pragma unroll
    for (int c = 0; c < 96; c++) {
        float d = As[c * 128 + tid] - mu;
        var += d * d;
    }
    var *= (1.f / 96.f);
    float rs = rsqrtf(var + EPSL);

    float* hb = g_h1 + (size_t)b * CC * TT + t;
    unsigned hu[48];
#pragma unroll
    for (int c = 0; c < 96; c += 2) {
        float v0 = (As[c * 128 + tid] - mu) * rs * G1[c] + B1[c];
        float v1 = (As[(c + 1) * 128 + tid] - mu) * rs * G1[c + 1] + B1[c + 1];
        hb[(size_t)c * TT] = v0;
        hb[(size_t)(c + 1) * TT] = v1;
        __half2 p = __floats2half2_rn(v0, v1);
        hu[c >> 1] = *reinterpret_cast<unsigned*>(&p);
    }
    uint4* dst = (uint4*)(g_h16 + ((size_t)b * TT + t) * 96);
#pragma unroll
    for (int q = 0; q < 12; q++)
        dst[q] = make_uint4(hu[4 * q], hu[4 * q + 1], hu[4 * q + 2], hu[4 * q + 3]);
}

// =====================================================================
// Kernel 4: FF, fp16 mma + cp.async double-buffered weight pipeline.
// =====================================================================
#define HS2 104
#define US2 72

__device__ __forceinline__ void stage_w(int jc, __half* W1d, __half* W2d, int tid) {
    const __half* w1h = g_w1h;
    const __half* w2h = g_w2h;
#pragma unroll
    for (int s = tid; s < 768; s += 512) {
        int r = s / 12, q = s - r * 12;
        cpa16(W1d + r * HS2 + q * 8, w1h + (size_t)(jc + r) * 96 + q * 8);
    }
#pragma unroll
    for (int s = tid; s < 768; s += 512) {
        int r = s >> 3, q = s & 7;
        cpa16(W2d + r * US2 + q * 8, w2h + (size_t)r * DFF + jc + q * 8);
    }
    cpa_commit();
}

__global__ __launch_bounds__(512, 1) void k_ff(const float* __restrict__ b1f,
                                               const float* __restrict__ b2f,
                                               const float* __restrict__ g2,
                                               const float* __restrict__ b2,
                                               const float* __restrict__ gf,
                                               const float* __restrict__ bf,
                                               float* __restrict__ out) {
    extern __shared__ char smraw[];
    __half* Hs  = (__half*)smraw;           // [128][104]
    __half* Us  = Hs + 128 * HS2;           // [128][72]
    __half* W1b = Us + 128 * US2;           // 2 x [64][104]
    __half* W2b = W1b + 2 * 64 * HS2;       // 2 x [96][72]
    __shared__ float B2F[96], G2S[96], B2S[96], GFS[96], BFS[96];

    int t0 = blockIdx.x * 128;
    int b  = blockIdx.y;
    int tid  = threadIdx.x;
    int lane = tid & 31;
    int w    = tid >> 5;
    int gid  = lane >> 2;
    int tig  = lane & 3;

    int m0u = (w & 3) * 32;    // tokens (u-phase)
    int n0u = (w >> 2) * 16;   // ff cols
    int m0y = (w & 3) * 32;    // tokens (y-phase)
    int n0y = (w >> 2) * 24;   // feature cols

    // prefetch chunk 0 weights, then load Hs
    stage_w(0, W1b, W2b, tid);

    const uint4* hsrc = (const uint4*)(g_h16 + ((size_t)b * TT + t0) * 96);
    for (int i = tid; i < 128 * 12; i += 512) {
        int tok = i / 12, seg = i - tok * 12;
        *(uint4*)(Hs + tok * HS2 + seg * 8) = hsrc[i];
    }
    if (tid < 96) {
        B2F[tid] = b2f[tid]; G2S[tid] = g2[tid]; B2S[tid] = b2[tid];
        GFS[tid] = gf[tid];  BFS[tid] = bf[tid];
    }

    float Y[2][3][4];
#pragma unroll
    for (int i = 0; i < 2; i++)
#pragma unroll
        for (int j = 0; j < 3; j++)
#pragma unroll
            for (int r = 0; r < 4; r++) Y[i][j][r] = 0.f;

    for (int c = 0; c < 32; c++) {
        int jc = c * 64;
        __half* W1c = W1b + (c & 1) * 64 * HS2;
        __half* W2c = W2b + (c & 1) * 96 * US2;

        cpa_wait_all();       // chunk c data landed (this thread's copies)
        __syncthreads();      // everyone's copies visible; y(c-1) fully done

        // ---- u-phase: ua = Hs(tile) @ W1c(tile)^T ----
        float ua[2][2][4];
#pragma unroll
        for (int i = 0; i < 2; i++)
#pragma unroll
            for (int j = 0; j < 2; j++)
#pragma unroll
                for (int r = 0; r < 4; r++) ua[i][j][r] = 0.f;

#pragma unroll
        for (int ks = 0; ks < 6; ks++) {
            int k0 = ks * 16;
            unsigned A[2][4], Bv[2][2];
#pragma unroll
            for (int i = 0; i < 2; i++) {
                const __half* base = Hs + (m0u + 16 * i + gid) * HS2 + k0 + 2 * tig;
                A[i][0] = *(const unsigned*)(base);
                A[i][1] = *(const unsigned*)(base + 8 * HS2);
                A[i][2] = *(const unsigned*)(base + 8);
                A[i][3] = *(const unsigned*)(base + 8 * HS2 + 8);
            }
#pragma unroll
            for (int j = 0; j < 2; j++) {
                const __half* bb = W1c + (n0u + 8 * j + gid) * HS2 + k0 + 2 * tig;
                Bv[j][0] = *(const unsigned*)(bb);
                Bv[j][1] = *(const unsigned*)(bb + 8);
            }
#pragma unroll
            for (int i = 0; i < 2; i++)
#pragma unroll
                for (int j = 0; j < 2; j++) mma16(ua[i][j], A[i], Bv[j]);
        }

        // bias + relu + store U
#pragma unroll
        for (int j = 0; j < 2; j++) {
            float2 bv = *(const float2*)(b1f + jc + n0u + 8 * j + 2 * tig);
#pragma unroll
            for (int i = 0; i < 2; i++) {
                __half2 lo = __floats2half2_rn(fmaxf(ua[i][j][0] + bv.x, 0.f),
                                               fmaxf(ua[i][j][1] + bv.y, 0.f));
                __half2 hi = __floats2half2_rn(fmaxf(ua[i][j][2] + bv.x, 0.f),
                                               fmaxf(ua[i][j][3] + bv.y, 0.f));
                *(__half2*)(Us + (m0u + 16 * i + gid) * US2 + n0u + 8 * j + 2 * tig)     = lo;
                *(__half2*)(Us + (m0u + 16 * i + gid + 8) * US2 + n0u + 8 * j + 2 * tig) = hi;
            }
        }
        __syncthreads();      // Us ready; all u-phase W1 reads done

        // prefetch chunk c+1 while y-phase computes
        if (c + 1 < 32)
            stage_w(jc + 64, W1b + ((c + 1) & 1) * 64 * HS2,
                    W2b + ((c + 1) & 1) * 96 * US2, tid);

        // ---- y-phase: Y += Us(tile) @ W2c(tile)^T ----
#pragma unroll
        for (int ks = 0; ks < 4; ks++) {
            int k0 = ks * 16;
            unsigned A[2][4], Bv[3][2];
#pragma unroll
            for (int i = 0; i < 2; i++) {
                const __half* base = Us + (m0y + 16 * i + gid) * US2 + k0 + 2 * tig;
                A[i][0] = *(const unsigned*)(base);
                A[i][1] = *(const unsigned*)(base + 8 * US2);
                A[i][2] = *(const unsigned*)(base + 8);
                A[i][3] = *(const unsigned*)(base + 8 * US2 + 8);
            }
#pragma unroll
            for (int j = 0; j < 3; j++) {
                const __half* bb = W2c + (n0y + 8 * j + gid) * US2 + k0 + 2 * tig;
                Bv[j][0] = *(const unsigned*)(bb);
                Bv[j][1] = *(const unsigned*)(bb + 8);
            }
#pragma unroll
            for (int i = 0; i < 2; i++)
#pragma unroll
                for (int j = 0; j < 3; j++) mma16(Y[i][j], A[i], Bv[j]);
        }
    }

    // epilogue: Y^T -> smem fp32, LN2 + LNf
    __syncthreads();
    float* Ys = (float*)smraw;
#pragma unroll
    for (int i = 0; i < 2; i++)
#pragma unroll
        for (int j = 0; j < 3; j++) {
            int row = m0y + 16 * i + gid;
            int col = n0y + 8 * j + 2 * tig;
            Ys[row * 101 + col]           = Y[i][j][0];
            Ys[row * 101 + col + 1]       = Y[i][j][1];
            Ys[(row + 8) * 101 + col]     = Y[i][j][2];
            Ys[(row + 8) * 101 + col + 1] = Y[i][j][3];
        }
    __syncthreads();

    if (tid < 128) {
        int t = tid;
        const float* h1p = g_h1 + (size_t)b * CC * TT + t0 + t;
        float* yr = Ys + t * 101;
        float mu = 0.f;
#pragma unroll
        for (int c = 0; c < 96; c++) {
            float v = yr[c] + h1p[(size_t)c * TT] + B2F[c];
            yr[c] = v;
            mu += v;
        }
        mu *= (1.f / 96.f);
        float var = 0.f;
#pragma unroll
        for (int c = 0; c < 96; c++) {
            float d = yr[c] - mu;
            var += d * d;
        }
        var *= (1.f / 96.f);
        float rs1 = rsqrtf(var + EPSL);

        float m2 = 0.f, s2 = 0.f;
#pragma unroll
        for (int c = 0; c < 96; c++) {
            float z = (yr[c] - mu) * rs1 * G2S[c] + B2S[c];
            yr[c] = z;
            m2 += z;
            s2 += z * z;
        }
        m2 *= (1.f / 96.f);
        float var2 = s2 * (1.f / 96.f) - m2 * m2;
        float rs2 = rsqrtf(var2 + EPSL);

        float* ob = out + (size_t)b * CC * TT + t0 + t;
        for (int c = 0; c < 96; c++)
            ob[(size_t)c * TT] = (yr[c] - m2) * rs2 * GFS[c] + BFS[c];
    }
}

// =====================================================================
extern "C" void kernel_launch(void* const* d_in, const int* in_sizes, int n_in,
                              void* d_out, int out_size) {
    const float* x     = (const float*)d_in[0];
    const float* w_qkv = (const float*)d_in[1];
    const float* b_qkv = (const float*)d_in[2];
    const float* w_out = (const float*)d_in[3];
    const float* b_out = (const float*)d_in[4];
    const float* ln1_g = (const float*)d_in[5];
    const float* ln1_b = (const float*)d_in[6];
    const float* w_ff1 = (const float*)d_in[7];
    const float* b_ff1 = (const float*)d_in[8];
    const float* w_ff2 = (const float*)d_in[9];
    const float* b_ff2 = (const float*)d_in[10];
    const float* ln2_g = (const float*)d_in[11];
    const float* ln2_b = (const float*)d_in[12];
    const float* lnf_g = (const float*)d_in[13];
    const float* lnf_b = (const float*)d_in[14];
    float* out = (float*)d_out;

    const int smem1 = (32 * 96 + 96 * 128) * 4;
    const int smem2 = (192 * 33 * 2 + 128 * 65) * 4;
    const int smem3 = (96 * 96 + 96 * 128) * 4;
    const int smem4 = (128 * HS2 + 128 * US2 + 2 * 64 * HS2 + 2 * 96 * US2) * 2;  // 99328

    cudaFuncSetAttribute(k_qkv,       cudaFuncAttributeMaxDynamicSharedMemorySize, smem1);
    cudaFuncSetAttribute(k_attn,      cudaFuncAttributeMaxDynamicSharedMemorySize, smem2);
    cudaFuncSetAttribute(k_oproj_ln1, cudaFuncAttributeMaxDynamicSharedMemorySize, smem3);
    cudaFuncSetAttribute(k_ff,        cudaFuncAttributeMaxDynamicSharedMemorySize, smem4);

    k_prep<<<(DFF * CC + 255) / 256, 256>>>(w_ff1, w_ff2);
    k_qkv<<<dim3(TT / 128, 9, BB), 256, smem1>>>(x, w_qkv, b_qkv);
    k_attn<<<dim3(TT / 128, NH, BB), 128, smem2>>>();
    k_oproj_ln1<<<dim3(TT / 128, BB), 128, smem3>>>(x, w_out, b_out, ln1_g, ln1_b);
    k_ff<<<dim3(TT / 128, BB), 512, smem4>>>(b_ff1, b_ff2, ln2_g, ln2_b,
                                             lnf_g, lnf_b, out);
}

// round 5
// speedup vs baseline: 7.3237x; 1.3940x over previous
#include <cuda_runtime.h>
#include <cuda_fp16.h>
#include <math.h>

#define BB   8
#define TT   2048
#define CC   96
#define NH   3
#define HD   32
#define DFF  2048
#define HW   32
#define NKEY 65
#define EPSL 1e-5f

// ---- scratch (device globals; no allocation allowed) ----
__device__ float  g_h1 [(size_t)BB * CC * TT];      // post-LN1 (fp32, feature-major)
__device__ __half g_h16[(size_t)BB * TT * CC];      // post-LN1 (fp16, token-major)
__device__ __half g_w1h[(size_t)DFF * CC];          // fp16 W1
__device__ __half g_w2h[(size_t)CC * DFF];          // fp16 W2
__device__ __half g_wqh[(size_t)3 * CC * CC];       // fp16 W_qkv
__device__ __half g_woh[(size_t)CC * CC];           // fp16 W_out
__device__ __half g_x16[(size_t)BB * TT * CC];      // x, token-major fp16
__device__ __half g_qkv16[(size_t)BB * TT * 3 * CC];// qkv, token-major fp16
__device__ __half g_c16[(size_t)BB * TT * CC];      // attention ctx, token-major fp16

// =====================================================================
__device__ __forceinline__ void mma16(float* d, const unsigned* a, const unsigned* b) {
    asm("mma.sync.aligned.m16n8k16.row.col.f32.f16.f16.f32 "
        "{%0,%1,%2,%3}, {%4,%5,%6,%7}, {%8,%9}, {%0,%1,%2,%3};"
        : "+f"(d[0]), "+f"(d[1]), "+f"(d[2]), "+f"(d[3])
        : "r"(a[0]), "r"(a[1]), "r"(a[2]), "r"(a[3]), "r"(b[0]), "r"(b[1]));
}
__device__ __forceinline__ void cpa16(void* dst, const void* src) {
    unsigned d = (unsigned)__cvta_generic_to_shared(dst);
    asm volatile("cp.async.cg.shared.global [%0], [%1], 16;" :: "r"(d), "l"(src));
}
__device__ __forceinline__ void cpa_commit() {
    asm volatile("cp.async.commit_group;" ::: "memory");
}
__device__ __forceinline__ void cpa_wait_all() {
    asm volatile("cp.async.wait_group 0;" ::: "memory");
}

// =====================================================================
// Kernel 0: weight prep (fp32 -> fp16) for W1, W2, Wqkv, Wout
// =====================================================================
__global__ __launch_bounds__(256) void k_prep(const float* __restrict__ w1,
                                              const float* __restrict__ w2,
                                              const float* __restrict__ wq,
                                              const float* __restrict__ wo) {
    int i = blockIdx.x * 256 + threadIdx.x;
    if (i < DFF * CC) {
        g_w1h[i] = __float2half_rn(w1[i]);
        g_w2h[i] = __float2half_rn(w2[i]);
    }
    if (i < 3 * CC * CC) g_wqh[i] = __float2half_rn(wq[i]);
    if (i < CC * CC)     g_woh[i] = __float2half_rn(wo[i]);
}

// =====================================================================
// Kernel 0b: x (B,C,T) fp32 -> g_x16 (B,T,C) fp16 transpose
// grid (T/32, 3, B), block (32,8)
// =====================================================================
__global__ __launch_bounds__(256) void k_xt(const float* __restrict__ x) {
    __shared__ float tile[32][33];
    int t0 = blockIdx.x * 32;
    int c0 = blockIdx.y * 32;
    int b  = blockIdx.z;
    int tx = threadIdx.x, ty = threadIdx.y;

    const float* xb = x + (size_t)b * CC * TT;
#pragma unroll
    for (int i = 0; i < 4; i++)
        tile[ty + 8 * i][tx] = xb[(size_t)(c0 + ty + 8 * i) * TT + t0 + tx];
    __syncthreads();
    __half* ob = g_x16 + (size_t)b * TT * CC;
#pragma unroll
    for (int i = 0; i < 4; i++)
        ob[(size_t)(t0 + ty + 8 * i) * CC + c0 + tx] =
            __float2half_rn(tile[tx][ty + 8 * i]);
}

// =====================================================================
// Kernel 1: QKV via fp16 mma. grid (16,8)=128 blocks, 512 threads.
// out[128 tok][288] = x16 @ Wqkv^T + b ; written token-major fp16.
// Warp tile: tokens (w&3)*32, feats (w>>2)*72 (3 sub-tiles of 24).
// =====================================================================
#define XS2 104

__global__ __launch_bounds__(512, 1) void k_qkv(const float* __restrict__ bias) {
    extern __shared__ char smraw[];
    __half* Xs = (__half*)smraw;        // [128][104]
    __half* Wq = Xs + 128 * XS2;        // [288][104]

    int t0 = blockIdx.x * 128;
    int b  = blockIdx.y;
    int tid  = threadIdx.x;
    int lane = tid & 31;
    int w    = tid >> 5;
    int gid  = lane >> 2;
    int tig  = lane & 3;
    int m0 = (w & 3) * 32;
    int g0 = (w >> 2) * 72;

    const uint4* xsrc = (const uint4*)(g_x16 + ((size_t)b * TT + t0) * 96);
    for (int i = tid; i < 128 * 12; i += 512) {
        int tok = i / 12, seg = i - tok * 12;
        *(uint4*)(Xs + tok * XS2 + seg * 8) = xsrc[i];
    }
    const uint4* wsrc = (const uint4*)g_wqh;
    for (int i = tid; i < 288 * 12; i += 512) {
        int r = i / 12, q = i - r * 12;
        *(uint4*)(Wq + r * XS2 + q * 8) = wsrc[i];
    }
    __syncthreads();

    float acc[3][2][3][4];
#pragma unroll
    for (int jt = 0; jt < 3; jt++)
#pragma unroll
        for (int i = 0; i < 2; i++)
#pragma unroll
            for (int jj = 0; jj < 3; jj++)
#pragma unroll
                for (int r = 0; r < 4; r++) acc[jt][i][jj][r] = 0.f;

#pragma unroll
    for (int ks = 0; ks < 6; ks++) {
        int k0 = ks * 16;
        unsigned A[2][4];
#pragma unroll
        for (int i = 0; i < 2; i++) {
            const __half* base = Xs + (m0 + 16 * i + gid) * XS2 + k0 + 2 * tig;
            A[i][0] = *(const unsigned*)(base);
            A[i][1] = *(const unsigned*)(base + 8 * XS2);
            A[i][2] = *(const unsigned*)(base + 8);
            A[i][3] = *(const unsigned*)(base + 8 * XS2 + 8);
        }
#pragma unroll
        for (int jt = 0; jt < 3; jt++) {
            unsigned Bv[3][2];
#pragma unroll
            for (int jj = 0; jj < 3; jj++) {
                const __half* bb = Wq + (g0 + 24 * jt + 8 * jj + gid) * XS2 + k0 + 2 * tig;
                Bv[jj][0] = *(const unsigned*)(bb);
                Bv[jj][1] = *(const unsigned*)(bb + 8);
            }
#pragma unroll
            for (int i = 0; i < 2; i++)
#pragma unroll
                for (int jj = 0; jj < 3; jj++) mma16(acc[jt][i][jj], A[i], Bv[jj]);
        }
    }

    // epilogue: + bias, fp16, token-major stores
    __half* ob = g_qkv16 + ((size_t)b * TT + t0) * 288;
#pragma unroll
    for (int jt = 0; jt < 3; jt++)
#pragma unroll
        for (int jj = 0; jj < 3; jj++) {
            int c = g0 + 24 * jt + 8 * jj + 2 * tig;
            float2 bv = *(const float2*)(bias + c);
#pragma unroll
            for (int i = 0; i < 2; i++) {
                int row = m0 + 16 * i + gid;
                __half2 lo = __floats2half2_rn(acc[jt][i][jj][0] + bv.x,
                                               acc[jt][i][jj][1] + bv.y);
                __half2 hi = __floats2half2_rn(acc[jt][i][jj][2] + bv.x,
                                               acc[jt][i][jj][3] + bv.y);
                *(__half2*)(ob + (size_t)row * 288 + c)       = lo;
                *(__half2*)(ob + (size_t)(row + 8) * 288 + c) = hi;
            }
        }
}

// =====================================================================
// Kernel 2: banded attention. Reads token-major fp16 qkv; fp32 compute;
// writes token-major fp16 ctx.
// =====================================================================
__global__ __launch_bounds__(128) void k_attn() {
    extern __shared__ float sm[];
    float* Ks = sm;              // [192][33]
    float* Vs = Ks + 192 * 33;   // [192][33]
    float* Sc = Vs + 192 * 33;   // [128][65]

    int t0 = blockIdx.x * 128;
    int h  = blockIdx.y;
    int b  = blockIdx.z;
    int tid = threadIdx.x;

    const __half* qkvb = g_qkv16 + (size_t)b * TT * 288;

    for (int r = tid; r < 192; r += 128) {
        int s = t0 - HW + r;
        bool ok = (s >= 0) && (s < TT);
        if (ok) {
            const uint4* kp = (const uint4*)(qkvb + (size_t)s * 288 + 96 + h * HD);
            const uint4* vp = (const uint4*)(qkvb + (size_t)s * 288 + 192 + h * HD);
#pragma unroll
            for (int q = 0; q < 4; q++) {
                uint4 ku = kp[q], vu = vp[q];
                const __half2* k2 = (const __half2*)&ku;
                const __half2* v2 = (const __half2*)&vu;
#pragma unroll
                for (int e = 0; e < 4; e++) {
                    float2 kf = __half22float2(k2[e]);
                    float2 vf = __half22float2(v2[e]);
                    Ks[r * 33 + q * 8 + 2 * e]     = kf.x;
                    Ks[r * 33 + q * 8 + 2 * e + 1] = kf.y;
                    Vs[r * 33 + q * 8 + 2 * e]     = vf.x;
                    Vs[r * 33 + q * 8 + 2 * e + 1] = vf.y;
                }
            }
        } else {
#pragma unroll
            for (int d = 0; d < 32; d++) {
                Ks[r * 33 + d] = 0.f;
                Vs[r * 33 + d] = 0.f;
            }
        }
    }
    __syncthreads();

    int t = t0 + tid;
    float q[32];
    {
        const uint4* qp = (const uint4*)(qkvb + (size_t)t * 288 + h * HD);
#pragma unroll
        for (int qq = 0; qq < 4; qq++) {
            uint4 u = qp[qq];
            const __half2* h2 = (const __half2*)&u;
#pragma unroll
            for (int e = 0; e < 4; e++) {
                float2 f = __half22float2(h2[e]);
                q[qq * 8 + 2 * e]     = f.x;
                q[qq * 8 + 2 * e + 1] = f.y;
            }
        }
    }

    const float scale = 0.17677669529663689f;
    float* scRow = Sc + tid * 65;
    float mx = -1e30f;
    for (int j = 0; j < NKEY; j++) {
        const float* kr = Ks + (tid + j) * 33;
        float a0 = 0.f, a1 = 0.f;
#pragma unroll
        for (int d = 0; d < 32; d += 2) {
            a0 += q[d] * kr[d];
            a1 += q[d + 1] * kr[d + 1];
        }
        float a = (a0 + a1) * scale;
        int s = t - HW + j;
        if (s < 0 || s >= TT) a = -1e30f;
        scRow[j] = a;
        mx = fmaxf(mx, a);
    }
    float sum = 0.f;
    for (int j = 0; j < NKEY; j++) {
        float e = __expf(scRow[j] - mx);
        scRow[j] = e;
        sum += e;
    }
    float inv = 1.f / sum;

    float ctx[32];
#pragma unroll
    for (int d = 0; d < 32; d++) ctx[d] = 0.f;
    for (int j = 0; j < NKEY; j++) {
        float p = scRow[j];
        const float* vr = Vs + (tid + j) * 33;
#pragma unroll
        for (int d = 0; d < 32; d++) ctx[d] += p * vr[d];
    }

    // token-major fp16 ctx
    unsigned cw[16];
#pragma unroll
    for (int d = 0; d < 32; d += 2) {
        __half2 p = __floats2half2_rn(ctx[d] * inv, ctx[d + 1] * inv);
        cw[d >> 1] = *reinterpret_cast<unsigned*>(&p);
    }
    uint4* cb = (uint4*)(g_c16 + ((size_t)b * TT + t) * 96 + h * HD);
#pragma unroll
    for (int qq = 0; qq < 4; qq++)
        cb[qq] = make_uint4(cw[4 * qq], cw[4 * qq + 1], cw[4 * qq + 2], cw[4 * qq + 3]);
}

// =====================================================================
// Kernel 3: out-proj (fp16 mma) + residual + LN1. grid (16,8), 512 thr.
// Warp tile: tokens (w&3)*32, feats (w>>2)*24. K=96.
// =====================================================================
__global__ __launch_bounds__(512, 1) void k_oproj_ln1(const float* __restrict__ x,
                                                      const float* __restrict__ bo,
                                                      const float* __restrict__ g1,
                                                      const float* __restrict__ b1) {
    extern __shared__ char smraw[];
    __half* Cs = (__half*)smraw;        // [128][104]
    __half* Wo = Cs + 128 * XS2;        // [96][104]
    __shared__ float BoS[96], G1S[96], B1S[96];

    int t0 = blockIdx.x * 128;
    int b  = blockIdx.y;
    int tid  = threadIdx.x;
    int lane = tid & 31;
    int w    = tid >> 5;
    int gid  = lane >> 2;
    int tig  = lane & 3;
    int m0 = (w & 3) * 32;
    int n0 = (w >> 2) * 24;

    const uint4* csrc = (const uint4*)(g_c16 + ((size_t)b * TT + t0) * 96);
    for (int i = tid; i < 128 * 12; i += 512) {
        int tok = i / 12, seg = i - tok * 12;
        *(uint4*)(Cs + tok * XS2 + seg * 8) = csrc[i];
    }
    const uint4* wsrc = (const uint4*)g_woh;
    for (int i = tid; i < 96 * 12; i += 512) {
        int r = i / 12, q = i - r * 12;
        *(uint4*)(Wo + r * XS2 + q * 8) = wsrc[i];
    }
    if (tid < 96) { BoS[tid] = bo[tid]; G1S[tid] = g1[tid]; B1S[tid] = b1[tid]; }
    __syncthreads();

    float Y[2][3][4];
#pragma unroll
    for (int i = 0; i < 2; i++)
#pragma unroll
        for (int j = 0; j < 3; j++)
#pragma unroll
            for (int r = 0; r < 4; r++) Y[i][j][r] = 0.f;

#pragma unroll
    for (int ks = 0; ks < 6; ks++) {
        int k0 = ks * 16;
        unsigned A[2][4], Bv[3][2];
#pragma unroll
        for (int i = 0; i < 2; i++) {
            const __half* base = Cs + (m0 + 16 * i + gid) * XS2 + k0 + 2 * tig;
            A[i][0] = *(const unsigned*)(base);
            A[i][1] = *(const unsigned*)(base + 8 * XS2);
            A[i][2] = *(const unsigned*)(base + 8);
            A[i][3] = *(const unsigned*)(base + 8 * XS2 + 8);
        }
#pragma unroll
        for (int j = 0; j < 3; j++) {
            const __half* bb = Wo + (n0 + 8 * j + gid) * XS2 + k0 + 2 * tig;
            Bv[j][0] = *(const unsigned*)(bb);
            Bv[j][1] = *(const unsigned*)(bb + 8);
        }
#pragma unroll
        for (int i = 0; i < 2; i++)
#pragma unroll
            for (int j = 0; j < 3; j++) mma16(Y[i][j], A[i], Bv[j]);
    }

    // Y -> smem fp32 (alias), then residual + LN1
    __syncthreads();
    float* Ys = (float*)smraw;   // [128][101]
#pragma unroll
    for (int i = 0; i < 2; i++)
#pragma unroll
        for (int j = 0; j < 3; j++) {
            int row = m0 + 16 * i + gid;
            int col = n0 + 8 * j + 2 * tig;
            Ys[row * 101 + col]           = Y[i][j][0];
            Ys[row * 101 + col + 1]       = Y[i][j][1];
            Ys[(row + 8) * 101 + col]     = Y[i][j][2];
            Ys[(row + 8) * 101 + col + 1] = Y[i][j][3];
        }
    __syncthreads();

    if (tid < 128) {
        int t = tid;
        const float* xb = x + (size_t)b * CC * TT + t0 + t;
        float* yr = Ys + t * 101;
        float mu = 0.f;
#pragma unroll
        for (int c = 0; c < 96; c++) {
            float v = yr[c] + xb[(size_t)c * TT] + BoS[c];
            yr[c] = v;
            mu += v;
        }
        mu *= (1.f / 96.f);
        float var = 0.f;
#pragma unroll
        for (int c = 0; c < 96; c++) {
            float d = yr[c] - mu;
            var += d * d;
        }
        var *= (1.f / 96.f);
        float rs = rsqrtf(var + EPSL);

        float* hb = g_h1 + (size_t)b * CC * TT + t0 + t;
        unsigned hu[48];
#pragma unroll
        for (int c = 0; c < 96; c += 2) {
            float v0 = (yr[c] - mu) * rs * G1S[c] + B1S[c];
            float v1 = (yr[c + 1] - mu) * rs * G1S[c + 1] + B1S[c + 1];
            hb[(size_t)c * TT] = v0;
            hb[(size_t)(c + 1) * TT] = v1;
            __half2 p = __floats2half2_rn(v0, v1);
            hu[c >> 1] = *reinterpret_cast<unsigned*>(&p);
        }
        uint4* dst = (uint4*)(g_h16 + ((size_t)b * TT + t0 + t) * 96);
#pragma unroll
        for (int qq = 0; qq < 12; qq++)
            dst[qq] = make_uint4(hu[4 * qq], hu[4 * qq + 1], hu[4 * qq + 2], hu[4 * qq + 3]);
    }
}

// =====================================================================
// Kernel 4: FF, fp16 mma + cp.async double-buffered pipeline (unchanged).
// =====================================================================
#define HS2 104
#define US2 72

__device__ __forceinline__ void stage_w(int jc, __half* W1d, __half* W2d, int tid) {
    const __half* w1h = g_w1h;
    const __half* w2h = g_w2h;
#pragma unroll
    for (int s = tid; s < 768; s += 512) {
        int r = s / 12, q = s - r * 12;
        cpa16(W1d + r * HS2 + q * 8, w1h + (size_t)(jc + r) * 96 + q * 8);
    }
#pragma unroll
    for (int s = tid; s < 768; s += 512) {
        int r = s >> 3, q = s & 7;
        cpa16(W2d + r * US2 + q * 8, w2h + (size_t)r * DFF + jc + q * 8);
    }
    cpa_commit();
}

__global__ __launch_bounds__(512, 1) void k_ff(const float* __restrict__ b1f,
                                               const float* __restrict__ b2f,
                                               const float* __restrict__ g2,
                                               const float* __restrict__ b2,
                                               const float* __restrict__ gf,
                                               const float* __restrict__ bf,
                                               float* __restrict__ out) {
    extern __shared__ char smraw[];
    __half* Hs  = (__half*)smraw;           // [128][104]
    __half* Us  = Hs + 128 * HS2;           // [128][72]
    __half* W1b = Us + 128 * US2;           // 2 x [64][104]
    __half* W2b = W1b + 2 * 64 * HS2;       // 2 x [96][72]
    __shared__ float B2F[96], G2S[96], B2S[96], GFS[96], BFS[96];

    int t0 = blockIdx.x * 128;
    int b  = blockIdx.y;
    int tid  = threadIdx.x;
    int lane = tid & 31;
    int w    = tid >> 5;
    int gid  = lane >> 2;
    int tig  = lane & 3;

    int m0u = (w & 3) * 32;
    int n0u = (w >> 2) * 16;
    int m0y = (w & 3) * 32;
    int n0y = (w >> 2) * 24;

    stage_w(0, W1b, W2b, tid);

    const uint4* hsrc = (const uint4*)(g_h16 + ((size_t)b * TT + t0) * 96);
    for (int i = tid; i < 128 * 12; i += 512) {
        int tok = i / 12, seg = i - tok * 12;
        *(uint4*)(Hs + tok * HS2 + seg * 8) = hsrc[i];
    }
    if (tid < 96) {
        B2F[tid] = b2f[tid]; G2S[tid] = g2[tid]; B2S[tid] = b2[tid];
        GFS[tid] = gf[tid];  BFS[tid] = bf[tid];
    }

    float Y[2][3][4];
#pragma unroll
    for (int i = 0; i < 2; i++)
#pragma unroll
        for (int j = 0; j < 3; j++)
#pragma unroll
            for (int r = 0; r < 4; r++) Y[i][j][r] = 0.f;

    for (int c = 0; c < 32; c++) {
        int jc = c * 64;
        __half* W1c = W1b + (c & 1) * 64 * HS2;
        __half* W2c = W2b + (c & 1) * 96 * US2;

        cpa_wait_all();
        __syncthreads();

        float ua[2][2][4];
#pragma unroll
        for (int i = 0; i < 2; i++)
#pragma unroll
            for (int j = 0; j < 2; j++)
#pragma unroll
                for (int r = 0; r < 4; r++) ua[i][j][r] = 0.f;

#pragma unroll
        for (int ks = 0; ks < 6; ks++) {
            int k0 = ks * 16;
            unsigned A[2][4], Bv[2][2];
#pragma unroll
            for (int i = 0; i < 2; i++) {
                const __half* base = Hs + (m0u + 16 * i + gid) * HS2 + k0 + 2 * tig;
                A[i][0] = *(const unsigned*)(base);
                A[i][1] = *(const unsigned*)(base + 8 * HS2);
                A[i][2] = *(const unsigned*)(base + 8);
                A[i][3] = *(const unsigned*)(base + 8 * HS2 + 8);
            }
#pragma unroll
            for (int j = 0; j < 2; j++) {
                const __half* bb = W1c + (n0u + 8 * j + gid) * HS2 + k0 + 2 * tig;
                Bv[j][0] = *(const unsigned*)(bb);
                Bv[j][1] = *(const unsigned*)(bb + 8);
            }
#pragma unroll
            for (int i = 0; i < 2; i++)
#pragma unroll
                for (int j = 0; j < 2; j++) mma16(ua[i][j], A[i], Bv[j]);
        }

#pragma unroll
        for (int j = 0; j < 2; j++) {
            float2 bv = *(const float2*)(b1f + jc + n0u + 8 * j + 2 * tig);
#pragma unroll
            for (int i = 0; i < 2; i++) {
                __half2 lo = __floats2half2_rn(fmaxf(ua[i][j][0] + bv.x, 0.f),
                                               fmaxf(ua[i][j][1] + bv.y, 0.f));
                __half2 hi = __floats2half2_rn(fmaxf(ua[i][j][2] + bv.x, 0.f),
                                               fmaxf(ua[i][j][3] + bv.y, 0.f));
                *(__half2*)(Us + (m0u + 16 * i + gid) * US2 + n0u + 8 * j + 2 * tig)     = lo;
                *(__half2*)(Us + (m0u + 16 * i + gid + 8) * US2 + n0u + 8 * j + 2 * tig) = hi;
            }
        }
        __syncthreads();

        if (c + 1 < 32)
            stage_w(jc + 64, W1b + ((c + 1) & 1) * 64 * HS2,
                    W2b + ((c + 1) & 1) * 96 * US2, tid);

#pragma unroll
        for (int ks = 0; ks < 4; ks++) {
            int k0 = ks * 16;
            unsigned A[2][4], Bv[3][2];
#pragma unroll
            for (int i = 0; i < 2; i++) {
                const __half* base = Us + (m0y + 16 * i + gid) * US2 + k0 + 2 * tig;
                A[i][0] = *(const unsigned*)(base);
                A[i][1] = *(const unsigned*)(base + 8 * US2);
                A[i][2] = *(const unsigned*)(base + 8);
                A[i][3] = *(const unsigned*)(base + 8 * US2 + 8);
            }
#pragma unroll
            for (int j = 0; j < 3; j++) {
                const __half* bb = W2c + (n0y + 8 * j + gid) * US2 + k0 + 2 * tig;
                Bv[j][0] = *(const unsigned*)(bb);
                Bv[j][1] = *(const unsigned*)(bb + 8);
            }
#pragma unroll
            for (int i = 0; i < 2; i++)
#pragma unroll
                for (int j = 0; j < 3; j++) mma16(Y[i][j], A[i], Bv[j]);
        }
    }

    __syncthreads();
    float* Ys = (float*)smraw;
#pragma unroll
    for (int i = 0; i < 2; i++)
#pragma unroll
        for (int j = 0; j < 3; j++) {
            int row = m0y + 16 * i + gid;
            int col = n0y + 8 * j + 2 * tig;
            Ys[row * 101 + col]           = Y[i][j][0];
            Ys[row * 101 + col + 1]       = Y[i][j][1];
            Ys[(row + 8) * 101 + col]     = Y[i][j][2];
            Ys[(row + 8) * 101 + col + 1] = Y[i][j][3];
        }
    __syncthreads();

    if (tid < 128) {
        int t = tid;
        const float* h1p = g_h1 + (size_t)b * CC * TT + t0 + t;
        float* yr = Ys + t * 101;
        float mu = 0.f;
#pragma unroll
        for (int c = 0; c < 96; c++) {
            float v = yr[c] + h1p[(size_t)c * TT] + B2F[c];
            yr[c] = v;
            mu += v;
        }
        mu *= (1.f / 96.f);
        float var = 0.f;
#pragma unroll
        for (int c = 0; c < 96; c++) {
            float d = yr[c] - mu;
            var += d * d;
        }
        var *= (1.f / 96.f);
        float rs1 = rsqrtf(var + EPSL);

        float m2 = 0.f, s2 = 0.f;
#pragma unroll
        for (int c = 0; c < 96; c++) {
            float z = (yr[c] - mu) * rs1 * G2S[c] + B2S[c];
            yr[c] = z;
            m2 += z;
            s2 += z * z;
        }
        m2 *= (1.f / 96.f);
        float var2 = s2 * (1.f / 96.f) - m2 * m2;
        float rs2 = rsqrtf(var2 + EPSL);

        float* ob = out + (size_t)b * CC * TT + t0 + t;
        for (int c = 0; c < 96; c++)
            ob[(size_t)c * TT] = (yr[c] - m2) * rs2 * GFS[c] + BFS[c];
    }
}

// =====================================================================
extern "C" void kernel_launch(void* const* d_in, const int* in_sizes, int n_in,
                              void* d_out, int out_size) {
    const float* x     = (const float*)d_in[0];
    const float* w_qkv = (const float*)d_in[1];
    const float* b_qkv = (const float*)d_in[2];
    const float* w_out = (const float*)d_in[3];
    const float* b_out = (const float*)d_in[4];
    const float* ln1_g = (const float*)d_in[5];
    const float* ln1_b = (const float*)d_in[6];
    const float* w_ff1 = (const float*)d_in[7];
    const float* b_ff1 = (const float*)d_in[8];
    const float* w_ff2 = (const float*)d_in[9];
    const float* b_ff2 = (const float*)d_in[10];
    const float* ln2_g = (const float*)d_in[11];
    const float* ln2_b = (const float*)d_in[12];
    const float* lnf_g = (const float*)d_in[13];
    const float* lnf_b = (const float*)d_in[14];
    float* out = (float*)d_out;

    const int smemQ = (128 * XS2 + 288 * XS2) * 2;                         // 86528
    const int smemA = (192 * 33 * 2 + 128 * 65) * 4;                       // 83968
    const int smemO = 128 * 101 * 4;                                       // 51712 (>= staging 46.6KB)
    const int smemF = (128 * HS2 + 128 * US2 + 2 * 64 * HS2 + 2 * 96 * US2) * 2;  // 99328

    cudaFuncSetAttribute(k_qkv,       cudaFuncAttributeMaxDynamicSharedMemorySize, smemQ);
    cudaFuncSetAttribute(k_attn,      cudaFuncAttributeMaxDynamicSharedMemorySize, smemA);
    cudaFuncSetAttribute(k_oproj_ln1, cudaFuncAttributeMaxDynamicSharedMemorySize, smemO);
    cudaFuncSetAttribute(k_ff,        cudaFuncAttributeMaxDynamicSharedMemorySize, smemF);

    k_prep<<<(DFF * CC + 255) / 256, 256>>>(w_ff1, w_ff2, w_qkv, w_out);
    k_xt<<<dim3(TT / 32, 3, BB), dim3(32, 8)>>>(x);
    k_qkv<<<dim3(TT / 128, BB), 512, smemQ>>>(b_qkv);
    k_attn<<<dim3(TT / 128, NH, BB), 128, smemA>>>();
    k_oproj_ln1<<<dim3(TT / 128, BB), 512, smemO>>>(x, b_out, ln1_g, ln1_b);
    k_ff<<<dim3(TT / 128, BB), 512, smemF>>>(b_ff1, b_ff2, ln2_g, ln2_b,
                                             lnf_g, lnf_b, out);
}

// round 6
// speedup vs baseline: 9.5923x; 1.3098x over previous
#include <cuda_runtime.h>
#include <cuda_fp16.h>
#include <math.h>

#define BB   8
#define TT   2048
#define CC   96
#define NH   3
#define HD   32
#define DFF  2048
#define HW   32
#define NKEY 65
#define EPSL 1e-5f

// ---- scratch (device globals; no allocation allowed) ----
__device__ float  g_h1 [(size_t)BB * CC * TT];      // post-LN1 (fp32, feature-major)
__device__ __half g_h16[(size_t)BB * TT * CC];      // post-LN1 (fp16, token-major)
__device__ __half g_w1h[(size_t)DFF * CC];          // fp16 W1
__device__ __half g_w2h[(size_t)CC * DFF];          // fp16 W2
__device__ __half g_wqh[(size_t)3 * CC * CC];       // fp16 W_qkv
__device__ __half g_woh[(size_t)CC * CC];           // fp16 W_out
__device__ __half g_x16[(size_t)BB * TT * CC];      // x, token-major fp16
__device__ __half g_qkv16[(size_t)BB * TT * 3 * CC];// qkv, token-major fp16
__device__ __half g_c16[(size_t)BB * TT * CC];      // attention ctx, token-major fp16

// =====================================================================
__device__ __forceinline__ void mma16(float* d, const unsigned* a, const unsigned* b) {
    asm("mma.sync.aligned.m16n8k16.row.col.f32.f16.f16.f32 "
        "{%0,%1,%2,%3}, {%4,%5,%6,%7}, {%8,%9}, {%0,%1,%2,%3};"
        : "+f"(d[0]), "+f"(d[1]), "+f"(d[2]), "+f"(d[3])
        : "r"(a[0]), "r"(a[1]), "r"(a[2]), "r"(a[3]), "r"(b[0]), "r"(b[1]));
}
__device__ __forceinline__ void cpa16(void* dst, const void* src) {
    unsigned d = (unsigned)__cvta_generic_to_shared(dst);
    asm volatile("cp.async.cg.shared.global [%0], [%1], 16;" :: "r"(d), "l"(src));
}
__device__ __forceinline__ void cpa_commit() {
    asm volatile("cp.async.commit_group;" ::: "memory");
}
__device__ __forceinline__ void cpa_wait_all() {
    asm volatile("cp.async.wait_group 0;" ::: "memory");
}

// =====================================================================
// Kernel 0: weight prep (fp32 -> fp16)
// =====================================================================
__global__ __launch_bounds__(256) void k_prep(const float* __restrict__ w1,
                                              const float* __restrict__ w2,
                                              const float* __restrict__ wq,
                                              const float* __restrict__ wo) {
    int i = blockIdx.x * 256 + threadIdx.x;
    if (i < DFF * CC) {
        g_w1h[i] = __float2half_rn(w1[i]);
        g_w2h[i] = __float2half_rn(w2[i]);
    }
    if (i < 3 * CC * CC) g_wqh[i] = __float2half_rn(wq[i]);
    if (i < CC * CC)     g_woh[i] = __float2half_rn(wo[i]);
}

// =====================================================================
// Kernel 0b: x (B,C,T) fp32 -> g_x16 (B,T,C) fp16 transpose
// =====================================================================
__global__ __launch_bounds__(256) void k_xt(const float* __restrict__ x) {
    __shared__ float tile[32][33];
    int t0 = blockIdx.x * 32;
    int c0 = blockIdx.y * 32;
    int b  = blockIdx.z;
    int tx = threadIdx.x, ty = threadIdx.y;

    const float* xb = x + (size_t)b * CC * TT;
#pragma unroll
    for (int i = 0; i < 4; i++)
        tile[ty + 8 * i][tx] = xb[(size_t)(c0 + ty + 8 * i) * TT + t0 + tx];
    __syncthreads();
    __half* ob = g_x16 + (size_t)b * TT * CC;
#pragma unroll
    for (int i = 0; i < 4; i++)
        ob[(size_t)(t0 + ty + 8 * i) * CC + c0 + tx] =
            __float2half_rn(tile[tx][ty + 8 * i]);
}

// =====================================================================
// Kernel 1: QKV via fp16 mma (unchanged from R5)
// =====================================================================
#define XS2 104

__global__ __launch_bounds__(512, 1) void k_qkv(const float* __restrict__ bias) {
    extern __shared__ char smraw[];
    __half* Xs = (__half*)smraw;        // [128][104]
    __half* Wq = Xs + 128 * XS2;        // [288][104]

    int t0 = blockIdx.x * 128;
    int b  = blockIdx.y;
    int tid  = threadIdx.x;
    int lane = tid & 31;
    int w    = tid >> 5;
    int gid  = lane >> 2;
    int tig  = lane & 3;
    int m0 = (w & 3) * 32;
    int g0 = (w >> 2) * 72;

    const uint4* xsrc = (const uint4*)(g_x16 + ((size_t)b * TT + t0) * 96);
    for (int i = tid; i < 128 * 12; i += 512) {
        int tok = i / 12, seg = i - tok * 12;
        *(uint4*)(Xs + tok * XS2 + seg * 8) = xsrc[i];
    }
    const uint4* wsrc = (const uint4*)g_wqh;
    for (int i = tid; i < 288 * 12; i += 512) {
        int r = i / 12, q = i - r * 12;
        *(uint4*)(Wq + r * XS2 + q * 8) = wsrc[i];
    }
    __syncthreads();

    float acc[3][2][3][4];
#pragma unroll
    for (int jt = 0; jt < 3; jt++)
#pragma unroll
        for (int i = 0; i < 2; i++)
#pragma unroll
            for (int jj = 0; jj < 3; jj++)
#pragma unroll
                for (int r = 0; r < 4; r++) acc[jt][i][jj][r] = 0.f;

#pragma unroll
    for (int ks = 0; ks < 6; ks++) {
        int k0 = ks * 16;
        unsigned A[2][4];
#pragma unroll
        for (int i = 0; i < 2; i++) {
            const __half* base = Xs + (m0 + 16 * i + gid) * XS2 + k0 + 2 * tig;
            A[i][0] = *(const unsigned*)(base);
            A[i][1] = *(const unsigned*)(base + 8 * XS2);
            A[i][2] = *(const unsigned*)(base + 8);
            A[i][3] = *(const unsigned*)(base + 8 * XS2 + 8);
        }
#pragma unroll
        for (int jt = 0; jt < 3; jt++) {
            unsigned Bv[3][2];
#pragma unroll
            for (int jj = 0; jj < 3; jj++) {
                const __half* bb = Wq + (g0 + 24 * jt + 8 * jj + gid) * XS2 + k0 + 2 * tig;
                Bv[jj][0] = *(const unsigned*)(bb);
                Bv[jj][1] = *(const unsigned*)(bb + 8);
            }
#pragma unroll
            for (int i = 0; i < 2; i++)
#pragma unroll
                for (int jj = 0; jj < 3; jj++) mma16(acc[jt][i][jj], A[i], Bv[jj]);
        }
    }

    __half* ob = g_qkv16 + ((size_t)b * TT + t0) * 288;
#pragma unroll
    for (int jt = 0; jt < 3; jt++)
#pragma unroll
        for (int jj = 0; jj < 3; jj++) {
            int c = g0 + 24 * jt + 8 * jj + 2 * tig;
            float2 bv = *(const float2*)(bias + c);
#pragma unroll
            for (int i = 0; i < 2; i++) {
                int row = m0 + 16 * i + gid;
                __half2 lo = __floats2half2_rn(acc[jt][i][jj][0] + bv.x,
                                               acc[jt][i][jj][1] + bv.y);
                __half2 hi = __floats2half2_rn(acc[jt][i][jj][2] + bv.x,
                                               acc[jt][i][jj][3] + bv.y);
                *(__half2*)(ob + (size_t)row * 288 + c)       = lo;
                *(__half2*)(ob + (size_t)(row + 8) * 288 + c) = hi;
            }
        }
}

// =====================================================================
// Kernel 2 (REWRITTEN): banded attention via fp16 mma.
// grid (T/64, NH, B) = 768 blocks, 128 threads (4 warps).
// Block: 64 queries, key span [t0-32, t0+95] = 128 keys.
// Warp w: queries m0 = w*16. S(16x128) in regs, softmax in regs,
// P repacked to A-frags, ctx = P @ V^T via mma.
// =====================================================================
#define QSTR 40
#define VSTR 136

__global__ __launch_bounds__(128, 1) void k_attn() {
    extern __shared__ char smraw[];
    __half* Qs = (__half*)smraw;         // [64][40]
    __half* Ks = Qs + 64 * QSTR;         // [128][40]
    __half* Vt = Ks + 128 * QSTR;        // [32][136]  (V transposed: feat x key)

    int t0 = blockIdx.x * 64;
    int h  = blockIdx.y;
    int b  = blockIdx.z;
    int tid  = threadIdx.x;
    int lane = tid & 31;
    int w    = tid >> 5;
    int gid  = lane >> 2;
    int tig  = lane & 3;
    int m0   = w * 16;
    int kbase = t0 - HW;

    const __half* qkvb = g_qkv16 + (size_t)b * TT * 288;

    // stage Q [64][32]
    for (int i = tid; i < 64 * 4; i += 128) {
        int r = i >> 2, seg = i & 3;
        *(uint4*)(Qs + r * QSTR + seg * 8) =
            *(const uint4*)(qkvb + (size_t)(t0 + r) * 288 + h * HD + seg * 8);
    }
    // stage K [128][32], zero outside [0,T)
    for (int i = tid; i < 128 * 4; i += 128) {
        int r = i >> 2, seg = i & 3;
        int s = kbase + r;
        uint4 v = make_uint4(0, 0, 0, 0);
        if (s >= 0 && s < TT)
            v = *(const uint4*)(qkvb + (size_t)s * 288 + 96 + h * HD + seg * 8);
        *(uint4*)(Ks + r * QSTR + seg * 8) = v;
    }
    // stage V^T [32][128]: thread tid handles key row tid
    {
        int r = tid;  // 0..127
        int s = kbase + r;
        uint4 vv[4];
        if (s >= 0 && s < TT) {
#pragma unroll
            for (int seg = 0; seg < 4; seg++)
                vv[seg] = *(const uint4*)(qkvb + (size_t)s * 288 + 192 + h * HD + seg * 8);
        } else {
#pragma unroll
            for (int seg = 0; seg < 4; seg++) vv[seg] = make_uint4(0, 0, 0, 0);
        }
        const __half* vh = (const __half*)vv;
#pragma unroll
        for (int f = 0; f < 32; f++) Vt[f * VSTR + r] = vh[f];
    }
    __syncthreads();

    // ---- S = Q @ K^T : 16 n-tiles of 8 keys, K=32 (2 ksteps) ----
    float s[16][4];
#pragma unroll
    for (int j = 0; j < 16; j++)
#pragma unroll
        for (int r = 0; r < 4; r++) s[j][r] = 0.f;

#pragma unroll
    for (int ks = 0; ks < 2; ks++) {
        int k0 = ks * 16;
        unsigned A[4];
        const __half* abase = Qs + (m0 + gid) * QSTR + k0 + 2 * tig;
        A[0] = *(const unsigned*)(abase);
        A[1] = *(const unsigned*)(abase + 8 * QSTR);
        A[2] = *(const unsigned*)(abase + 8);
        A[3] = *(const unsigned*)(abase + 8 * QSTR + 8);
#pragma unroll
        for (int j = 0; j < 16; j++) {
            unsigned Bv[2];
            const __half* bb = Ks + (8 * j + gid) * QSTR + k0 + 2 * tig;
            Bv[0] = *(const unsigned*)(bb);
            Bv[1] = *(const unsigned*)(bb + 8);
            mma16(s[j], A, Bv);
        }
    }

    // ---- softmax over 128 key-cols (band mask -> -1e30) ----
    const float scale = 0.17677669529663689f;
    int row0 = m0 + gid;       // local query row (elems 0,1)
    int row1 = row0 + 8;       // elems 2,3
    float mx0 = -1e30f, mx1 = -1e30f;
#pragma unroll
    for (int j = 0; j < 16; j++) {
#pragma unroll
        for (int c = 0; c < 2; c++) {
            int col = 8 * j + 2 * tig + c;
            int key = kbase + col;
            bool in = (key >= 0) && (key < TT);
            bool v0 = in && (col >= row0) && (col <= row0 + 64);
            bool v1 = in && (col >= row1) && (col <= row1 + 64);
            s[j][c]     = v0 ? s[j][c] * scale     : -1e30f;
            s[j][c + 2] = v1 ? s[j][c + 2] * scale : -1e30f;
            mx0 = fmaxf(mx0, s[j][c]);
            mx1 = fmaxf(mx1, s[j][c + 2]);
        }
    }
    mx0 = fmaxf(mx0, __shfl_xor_sync(0xffffffffu, mx0, 1));
    mx0 = fmaxf(mx0, __shfl_xor_sync(0xffffffffu, mx0, 2));
    mx1 = fmaxf(mx1, __shfl_xor_sync(0xffffffffu, mx1, 1));
    mx1 = fmaxf(mx1, __shfl_xor_sync(0xffffffffu, mx1, 2));

    float sum0 = 0.f, sum1 = 0.f;
#pragma unroll
    for (int j = 0; j < 16; j++) {
        s[j][0] = __expf(s[j][0] - mx0);  sum0 += s[j][0];
        s[j][1] = __expf(s[j][1] - mx0);  sum0 += s[j][1];
        s[j][2] = __expf(s[j][2] - mx1);  sum1 += s[j][2];
        s[j][3] = __expf(s[j][3] - mx1);  sum1 += s[j][3];
    }
    sum0 += __shfl_xor_sync(0xffffffffu, sum0, 1);
    sum0 += __shfl_xor_sync(0xffffffffu, sum0, 2);
    sum1 += __shfl_xor_sync(0xffffffffu, sum1, 1);
    sum1 += __shfl_xor_sync(0xffffffffu, sum1, 2);
    float inv0 = 1.f / sum0, inv1 = 1.f / sum1;

    // repack P to fp16 A-fragments: pa[kt] covers keys 16kt..16kt+15
    unsigned pa[8][4];
#pragma unroll
    for (int kt = 0; kt < 8; kt++) {
        __half2 a0 = __floats2half2_rn(s[2 * kt][0] * inv0,     s[2 * kt][1] * inv0);
        __half2 a1 = __floats2half2_rn(s[2 * kt][2] * inv1,     s[2 * kt][3] * inv1);
        __half2 a2 = __floats2half2_rn(s[2 * kt + 1][0] * inv0, s[2 * kt + 1][1] * inv0);
        __half2 a3 = __floats2half2_rn(s[2 * kt + 1][2] * inv1, s[2 * kt + 1][3] * inv1);
        pa[kt][0] = *reinterpret_cast<unsigned*>(&a0);
        pa[kt][1] = *reinterpret_cast<unsigned*>(&a1);
        pa[kt][2] = *reinterpret_cast<unsigned*>(&a2);
        pa[kt][3] = *reinterpret_cast<unsigned*>(&a3);
    }

    // ---- ctx = P @ V^T : 4 n-tiles of 8 feats, 8 ksteps ----
    float o[4][4];
#pragma unroll
    for (int n = 0; n < 4; n++)
#pragma unroll
        for (int r = 0; r < 4; r++) o[n][r] = 0.f;

#pragma unroll
    for (int kt = 0; kt < 8; kt++) {
#pragma unroll
        for (int n = 0; n < 4; n++) {
            unsigned Bv[2];
            const __half* bb = Vt + (8 * n + gid) * VSTR + 16 * kt + 2 * tig;
            Bv[0] = *(const unsigned*)(bb);
            Bv[1] = *(const unsigned*)(bb + 8);
            mma16(o[n], pa[kt], Bv);
        }
    }

    // write ctx token-major fp16
    __half* cb = g_c16 + ((size_t)b * TT) * 96 + h * HD;
#pragma unroll
    for (int n = 0; n < 4; n++) {
        int col = 8 * n + 2 * tig;
        __half2 lo = __floats2half2_rn(o[n][0], o[n][1]);
        __half2 hi = __floats2half2_rn(o[n][2], o[n][3]);
        *(__half2*)(cb + (size_t)(t0 + row0) * 96 + col) = lo;
        *(__half2*)(cb + (size_t)(t0 + row1) * 96 + col) = hi;
    }
}

// =====================================================================
// Kernel 3: out-proj (fp16 mma) + residual + LN1 (unchanged from R5)
// =====================================================================
__global__ __launch_bounds__(512, 1) void k_oproj_ln1(const float* __restrict__ x,
                                                      const float* __restrict__ bo,
                                                      const float* __restrict__ g1,
                                                      const float* __restrict__ b1) {
    extern __shared__ char smraw[];
    __half* Cs = (__half*)smraw;        // [128][104]
    __half* Wo = Cs + 128 * XS2;        // [96][104]
    __shared__ float BoS[96], G1S[96], B1S[96];

    int t0 = blockIdx.x * 128;
    int b  = blockIdx.y;
    int tid  = threadIdx.x;
    int lane = tid & 31;
    int w    = tid >> 5;
    int gid  = lane >> 2;
    int tig  = lane & 3;
    int m0 = (w & 3) * 32;
    int n0 = (w >> 2) * 24;

    const uint4* csrc = (const uint4*)(g_c16 + ((size_t)b * TT + t0) * 96);
    for (int i = tid; i < 128 * 12; i += 512) {
        int tok = i / 12, seg = i - tok * 12;
        *(uint4*)(Cs + tok * XS2 + seg * 8) = csrc[i];
    }
    const uint4* wsrc = (const uint4*)g_woh;
    for (int i = tid; i < 96 * 12; i += 512) {
        int r = i / 12, q = i - r * 12;
        *(uint4*)(Wo + r * XS2 + q * 8) = wsrc[i];
    }
    if (tid < 96) { BoS[tid] = bo[tid]; G1S[tid] = g1[tid]; B1S[tid] = b1[tid]; }
    __syncthreads();

    float Y[2][3][4];
#pragma unroll
    for (int i = 0; i < 2; i++)
#pragma unroll
        for (int j = 0; j < 3; j++)
#pragma unroll
            for (int r = 0; r < 4; r++) Y[i][j][r] = 0.f;

#pragma unroll
    for (int ks = 0; ks < 6; ks++) {
        int k0 = ks * 16;
        unsigned A[2][4], Bv[3][2];
#pragma unroll
        for (int i = 0; i < 2; i++) {
            const __half* base = Cs + (m0 + 16 * i + gid) * XS2 + k0 + 2 * tig;
            A[i][0] = *(const unsigned*)(base);
            A[i][1] = *(const unsigned*)(base + 8 * XS2);
            A[i][2] = *(const unsigned*)(base + 8);
            A[i][3] = *(const unsigned*)(base + 8 * XS2 + 8);
        }
#pragma unroll
        for (int j = 0; j < 3; j++) {
            const __half* bb = Wo + (n0 + 8 * j + gid) * XS2 + k0 + 2 * tig;
            Bv[j][0] = *(const unsigned*)(bb);
            Bv[j][1] = *(const unsigned*)(bb + 8);
        }
#pragma unroll
        for (int i = 0; i < 2; i++)
#pragma unroll
            for (int j = 0; j < 3; j++) mma16(Y[i][j], A[i], Bv[j]);
    }

    __syncthreads();
    float* Ys = (float*)smraw;   // [128][101]
#pragma unroll
    for (int i = 0; i < 2; i++)
#pragma unroll
        for (int j = 0; j < 3; j++) {
            int row = m0 + 16 * i + gid;
            int col = n0 + 8 * j + 2 * tig;
            Ys[row * 101 + col]           = Y[i][j][0];
            Ys[row * 101 + col + 1]       = Y[i][j][1];
            Ys[(row + 8) * 101 + col]     = Y[i][j][2];
            Ys[(row + 8) * 101 + col + 1] = Y[i][j][3];
        }
    __syncthreads();

    if (tid < 128) {
        int t = tid;
        const float* xb = x + (size_t)b * CC * TT + t0 + t;
        float* yr = Ys + t * 101;
        float mu = 0.f;
#pragma unroll
        for (int c = 0; c < 96; c++) {
            float v = yr[c] + xb[(size_t)c * TT] + BoS[c];
            yr[c] = v;
            mu += v;
        }
        mu *= (1.f / 96.f);
        float var = 0.f;
#pragma unroll
        for (int c = 0; c < 96; c++) {
            float d = yr[c] - mu;
            var += d * d;
        }
        var *= (1.f / 96.f);
        float rs = rsqrtf(var + EPSL);

        float* hb = g_h1 + (size_t)b * CC * TT + t0 + t;
        unsigned hu[48];
#pragma unroll
        for (int c = 0; c < 96; c += 2) {
            float v0 = (yr[c] - mu) * rs * G1S[c] + B1S[c];
            float v1 = (yr[c + 1] - mu) * rs * G1S[c + 1] + B1S[c + 1];
            hb[(size_t)c * TT] = v0;
            hb[(size_t)(c + 1) * TT] = v1;
            __half2 p = __floats2half2_rn(v0, v1);
            hu[c >> 1] = *reinterpret_cast<unsigned*>(&p);
        }
        uint4* dst = (uint4*)(g_h16 + ((size_t)b * TT + t0 + t) * 96);
#pragma unroll
        for (int qq = 0; qq < 12; qq++)
            dst[qq] = make_uint4(hu[4 * qq], hu[4 * qq + 1], hu[4 * qq + 2], hu[4 * qq + 3]);
    }
}

// =====================================================================
// Kernel 4: FF (unchanged from R4/R5)
// =====================================================================
#define HS2 104
#define US2 72

__device__ __forceinline__ void stage_w(int jc, __half* W1d, __half* W2d, int tid) {
    const __half* w1h = g_w1h;
    const __half* w2h = g_w2h;
#pragma unroll
    for (int s = tid; s < 768; s += 512) {
        int r = s / 12, q = s - r * 12;
        cpa16(W1d + r * HS2 + q * 8, w1h + (size_t)(jc + r) * 96 + q * 8);
    }
#pragma unroll
    for (int s = tid; s < 768; s += 512) {
        int r = s >> 3, q = s & 7;
        cpa16(W2d + r * US2 + q * 8, w2h + (size_t)r * DFF + jc + q * 8);
    }
    cpa_commit();
}

__global__ __launch_bounds__(512, 1) void k_ff(const float* __restrict__ b1f,
                                               const float* __restrict__ b2f,
                                               const float* __restrict__ g2,
                                               const float* __restrict__ b2,
                                               const float* __restrict__ gf,
                                               const float* __restrict__ bf,
                                               float* __restrict__ out) {
    extern __shared__ char smraw[];
    __half* Hs  = (__half*)smraw;           // [128][104]
    __half* Us  = Hs + 128 * HS2;           // [128][72]
    __half* W1b = Us + 128 * US2;           // 2 x [64][104]
    __half* W2b = W1b + 2 * 64 * HS2;       // 2 x [96][72]
    __shared__ float B2F[96], G2S[96], B2S[96], GFS[96], BFS[96];

    int t0 = blockIdx.x * 128;
    int b  = blockIdx.y;
    int tid  = threadIdx.x;
    int lane = tid & 31;
    int w    = tid >> 5;
    int gid  = lane >> 2;
    int tig  = lane & 3;

    int m0u = (w & 3) * 32;
    int n0u = (w >> 2) * 16;
    int m0y = (w & 3) * 32;
    int n0y = (w >> 2) * 24;

    stage_w(0, W1b, W2b, tid);

    const uint4* hsrc = (const uint4*)(g_h16 + ((size_t)b * TT + t0) * 96);
    for (int i = tid; i < 128 * 12; i += 512) {
        int tok = i / 12, seg = i - tok * 12;
        *(uint4*)(Hs + tok * HS2 + seg * 8) = hsrc[i];
    }
    if (tid < 96) {
        B2F[tid] = b2f[tid]; G2S[tid] = g2[tid]; B2S[tid] = b2[tid];
        GFS[tid] = gf[tid];  BFS[tid] = bf[tid];
    }

    float Y[2][3][4];
#pragma unroll
    for (int i = 0; i < 2; i++)
#pragma unroll
        for (int j = 0; j < 3; j++)
#pragma unroll
            for (int r = 0; r < 4; r++) Y[i][j][r] = 0.f;

    for (int c = 0; c < 32; c++) {
        int jc = c * 64;
        __half* W1c = W1b + (c & 1) * 64 * HS2;
        __half* W2c = W2b + (c & 1) * 96 * US2;

        cpa_wait_all();
        __syncthreads();

        float ua[2][2][4];
#pragma unroll
        for (int i = 0; i < 2; i++)
#pragma unroll
            for (int j = 0; j < 2; j++)
#pragma unroll
                for (int r = 0; r < 4; r++) ua[i][j][r] = 0.f;

#pragma unroll
        for (int ks = 0; ks < 6; ks++) {
            int k0 = ks * 16;
            unsigned A[2][4], Bv[2][2];
#pragma unroll
            for (int i = 0; i < 2; i++) {
                const __half* base = Hs + (m0u + 16 * i + gid) * HS2 + k0 + 2 * tig;
                A[i][0] = *(const unsigned*)(base);
                A[i][1] = *(const unsigned*)(base + 8 * HS2);
                A[i][2] = *(const unsigned*)(base + 8);
                A[i][3] = *(const unsigned*)(base + 8 * HS2 + 8);
            }
#pragma unroll
            for (int j = 0; j < 2; j++) {
                const __half* bb = W1c + (n0u + 8 * j + gid) * HS2 + k0 + 2 * tig;
                Bv[j][0] = *(const unsigned*)(bb);
                Bv[j][1] = *(const unsigned*)(bb + 8);
            }
#pragma unroll
            for (int i = 0; i < 2; i++)
#pragma unroll
                for (int j = 0; j < 2; j++) mma16(ua[i][j], A[i], Bv[j]);
        }

#pragma unroll
        for (int j = 0; j < 2; j++) {
            float2 bv = *(const float2*)(b1f + jc + n0u + 8 * j + 2 * tig);
#pragma unroll
            for (int i = 0; i < 2; i++) {
                __half2 lo = __floats2half2_rn(fmaxf(ua[i][j][0] + bv.x, 0.f),
                                               fmaxf(ua[i][j][1] + bv.y, 0.f));
                __half2 hi = __floats2half2_rn(fmaxf(ua[i][j][2] + bv.x, 0.f),
                                               fmaxf(ua[i][j][3] + bv.y, 0.f));
                *(__half2*)(Us + (m0u + 16 * i + gid) * US2 + n0u + 8 * j + 2 * tig)     = lo;
                *(__half2*)(Us + (m0u + 16 * i + gid + 8) * US2 + n0u + 8 * j + 2 * tig) = hi;
            }
        }
        __syncthreads();

        if (c + 1 < 32)
            stage_w(jc + 64, W1b + ((c + 1) & 1) * 64 * HS2,
                    W2b + ((c + 1) & 1) * 96 * US2, tid);

#pragma unroll
        for (int ks = 0; ks < 4; ks++) {
            int k0 = ks * 16;
            unsigned A[2][4], Bv[3][2];
#pragma unroll
            for (int i = 0; i < 2; i++) {
                const __half* base = Us + (m0y + 16 * i + gid) * US2 + k0 + 2 * tig;
                A[i][0] = *(const unsigned*)(base);
                A[i][1] = *(const unsigned*)(base + 8 * US2);
                A[i][2] = *(const unsigned*)(base + 8);
                A[i][3] = *(const unsigned*)(base + 8 * US2 + 8);
            }
#pragma unroll
            for (int j = 0; j < 3; j++) {
                const __half* bb = W2c + (n0y + 8 * j + gid) * US2 + k0 + 2 * tig;
                Bv[j][0] = *(const unsigned*)(bb);
                Bv[j][1] = *(const unsigned*)(bb + 8);
            }
#pragma unroll
            for (int i = 0; i < 2; i++)
#pragma unroll
                for (int j = 0; j < 3; j++) mma16(Y[i][j], A[i], Bv[j]);
        }
    }

    __syncthreads();
    float* Ys = (float*)smraw;
#pragma unroll
    for (int i = 0; i < 2; i++)
#pragma unroll
        for (int j = 0; j < 3; j++) {
            int row = m0y + 16 * i + gid;
            int col = n0y + 8 * j + 2 * tig;
            Ys[row * 101 + col]           = Y[i][j][0];
            Ys[row * 101 + col + 1]       = Y[i][j][1];
            Ys[(row + 8) * 101 + col]     = Y[i][j][2];
            Ys[(row + 8) * 101 + col + 1] = Y[i][j][3];
        }
    __syncthreads();

    if (tid < 128) {
        int t = tid;
        const float* h1p = g_h1 + (size_t)b * CC * TT + t0 + t;
        float* yr = Ys + t * 101;
        float mu = 0.f;
#pragma unroll
        for (int c = 0; c < 96; c++) {
            float v = yr[c] + h1p[(size_t)c * TT] + B2F[c];
            yr[c] = v;
            mu += v;
        }
        mu *= (1.f / 96.f);
        float var = 0.f;
#pragma unroll
        for (int c = 0; c < 96; c++) {
            float d = yr[c] - mu;
            var += d * d;
        }
        var *= (1.f / 96.f);
        float rs1 = rsqrtf(var + EPSL);

        float m2 = 0.f, s2 = 0.f;
#pragma unroll
        for (int c = 0; c < 96; c++) {
            float z = (yr[c] - mu) * rs1 * G2S[c] + B2S[c];
            yr[c] = z;
            m2 += z;
            s2 += z * z;
        }
        m2 *= (1.f / 96.f);
        float var2 = s2 * (1.f / 96.f) - m2 * m2;
        float rs2 = rsqrtf(var2 + EPSL);

        float* ob = out + (size_t)b * CC * TT + t0 + t;
        for (int c = 0; c < 96; c++)
            ob[(size_t)c * TT] = (yr[c] - m2) * rs2 * GFS[c] + BFS[c];
    }
}

// =====================================================================
extern "C" void kernel_launch(void* const* d_in, const int* in_sizes, int n_in,
                              void* d_out, int out_size) {
    const float* x     = (const float*)d_in[0];
    const float* w_qkv = (const float*)d_in[1];
    const float* b_qkv = (const float*)d_in[2];
    const float* w_out = (const float*)d_in[3];
    const float* b_out = (const float*)d_in[4];
    const float* ln1_g = (const float*)d_in[5];
    const float* ln1_b = (const float*)d_in[6];
    const float* w_ff1 = (const float*)d_in[7];
    const float* b_ff1 = (const float*)d_in[8];
    const float* w_ff2 = (const float*)d_in[9];
    const float* b_ff2 = (const float*)d_in[10];
    const float* ln2_g = (const float*)d_in[11];
    const float* ln2_b = (const float*)d_in[12];
    const float* lnf_g = (const float*)d_in[13];
    const float* lnf_b = (const float*)d_in[14];
    float* out = (float*)d_out;

    const int smemQ = (128 * XS2 + 288 * XS2) * 2;                         // 86528
    const int smemA = (64 * QSTR + 128 * QSTR + 32 * VSTR) * 2;            // 24064
    const int smemO = 128 * 101 * 4;                                       // 51712
    const int smemF = (128 * HS2 + 128 * US2 + 2 * 64 * HS2 + 2 * 96 * US2) * 2;  // 99328

    cudaFuncSetAttribute(k_qkv,       cudaFuncAttributeMaxDynamicSharedMemorySize, smemQ);
    cudaFuncSetAttribute(k_attn,      cudaFuncAttributeMaxDynamicSharedMemorySize, smemA);
    cudaFuncSetAttribute(k_oproj_ln1, cudaFuncAttributeMaxDynamicSharedMemorySize, smemO);
    cudaFuncSetAttribute(k_ff,        cudaFuncAttributeMaxDynamicSharedMemorySize, smemF);

    k_prep<<<(DFF * CC + 255) / 256, 256>>>(w_ff1, w_ff2, w_qkv, w_out);
    k_xt<<<dim3(TT / 32, 3, BB), dim3(32, 8)>>>(x);
    k_qkv<<<dim3(TT / 128, BB), 512, smemQ>>>(b_qkv);
    k_attn<<<dim3(TT / 64, NH, BB), 128, smemA>>>();
    k_oproj_ln1<<<dim3(TT / 128, BB), 512, smemO>>>(x, b_out, ln1_g, ln1_b);
    k_ff<<<dim3(TT / 128, BB), 512, smemF>>>(b_ff1, b_ff2, ln2_g, ln2_b,
                                             lnf_g, lnf_b, out);
}

// round 7
// speedup vs baseline: 9.6370x; 1.0047x over previous
#include <cuda_runtime.h>
#include <cuda_fp16.h>
#include <math.h>

#define BB   8
#define TT   2048
#define CC   96
#define NH   3
#define HD   32
#define DFF  2048
#define HW   32
#define NKEY 65
#define EPSL 1e-5f

// ---- scratch (device globals; no allocation allowed) ----
__device__ float  g_h1 [(size_t)BB * CC * TT];      // post-LN1 (fp32, feature-major)
__device__ __half g_h16[(size_t)BB * TT * CC];      // post-LN1 (fp16, token-major)
__device__ __half g_w1h[(size_t)DFF * CC];          // fp16 W1
__device__ __half g_w2h[(size_t)CC * DFF];          // fp16 W2
__device__ __half g_wqh[(size_t)3 * CC * CC];       // fp16 W_qkv
__device__ __half g_woh[(size_t)CC * CC];           // fp16 W_out
__device__ __half g_x16[(size_t)BB * TT * CC];      // x, token-major fp16
__device__ __half g_qkv16[(size_t)BB * TT * 3 * CC];// qkv, token-major fp16

// =====================================================================
__device__ __forceinline__ void mma16(float* d, const unsigned* a, const unsigned* b) {
    asm("mma.sync.aligned.m16n8k16.row.col.f32.f16.f16.f32 "
        "{%0,%1,%2,%3}, {%4,%5,%6,%7}, {%8,%9}, {%0,%1,%2,%3};"
        : "+f"(d[0]), "+f"(d[1]), "+f"(d[2]), "+f"(d[3])
        : "r"(a[0]), "r"(a[1]), "r"(a[2]), "r"(a[3]), "r"(b[0]), "r"(b[1]));
}
__device__ __forceinline__ void cpa16(void* dst, const void* src) {
    unsigned d = (unsigned)__cvta_generic_to_shared(dst);
    asm volatile("cp.async.cg.shared.global [%0], [%1], 16;" :: "r"(d), "l"(src));
}
__device__ __forceinline__ void cpa_commit() {
    asm volatile("cp.async.commit_group;" ::: "memory");
}
__device__ __forceinline__ void cpa_wait_all() {
    asm volatile("cp.async.wait_group 0;" ::: "memory");
}

// =====================================================================
// Kernel 0 (MERGED): weight prep + x transpose in one launch.
// Blocks [0, 768): fp32->fp16 weights.  Blocks [768, 2304): x transpose.
// =====================================================================
#define PREP_BLKS 768

__global__ __launch_bounds__(256) void k_prep(const float* __restrict__ w1,
                                              const float* __restrict__ w2,
                                              const float* __restrict__ wq,
                                              const float* __restrict__ wo,
                                              const float* __restrict__ x) {
    int bx = blockIdx.x;
    if (bx < PREP_BLKS) {
        int i = bx * 256 + threadIdx.x;
        if (i < DFF * CC) {
            g_w1h[i] = __float2half_rn(w1[i]);
            g_w2h[i] = __float2half_rn(w2[i]);
        }
        if (i < 3 * CC * CC) g_wqh[i] = __float2half_rn(wq[i]);
        if (i < CC * CC)     g_woh[i] = __float2half_rn(wo[i]);
        return;
    }
    // x transpose part
    __shared__ float tile[32][33];
    int bx2 = bx - PREP_BLKS;
    int tI = bx2 & 63;          // 64 token tiles
    int rest = bx2 >> 6;
    int cI = rest % 3;
    int b  = rest / 3;
    int t0 = tI * 32;
    int c0 = cI * 32;
    int tx = threadIdx.x & 31, ty = threadIdx.x >> 5;

    const float* xb = x + (size_t)b * CC * TT;
#pragma unroll
    for (int i = 0; i < 4; i++)
        tile[ty + 8 * i][tx] = xb[(size_t)(c0 + ty + 8 * i) * TT + t0 + tx];
    __syncthreads();
    __half* ob = g_x16 + (size_t)b * TT * CC;
#pragma unroll
    for (int i = 0; i < 4; i++)
        ob[(size_t)(t0 + ty + 8 * i) * CC + c0 + tx] =
            __float2half_rn(tile[tx][ty + 8 * i]);
}

// =====================================================================
// Kernel 1: QKV via fp16 mma (unchanged from R5/R6)
// =====================================================================
#define XS2 104

__global__ __launch_bounds__(512, 1) void k_qkv(const float* __restrict__ bias) {
    extern __shared__ char smraw[];
    __half* Xs = (__half*)smraw;        // [128][104]
    __half* Wq = Xs + 128 * XS2;        // [288][104]

    int t0 = blockIdx.x * 128;
    int b  = blockIdx.y;
    int tid  = threadIdx.x;
    int lane = tid & 31;
    int w    = tid >> 5;
    int gid  = lane >> 2;
    int tig  = lane & 3;
    int m0 = (w & 3) * 32;
    int g0 = (w >> 2) * 72;

    const uint4* xsrc = (const uint4*)(g_x16 + ((size_t)b * TT + t0) * 96);
    for (int i = tid; i < 128 * 12; i += 512) {
        int tok = i / 12, seg = i - tok * 12;
        *(uint4*)(Xs + tok * XS2 + seg * 8) = xsrc[i];
    }
    const uint4* wsrc = (const uint4*)g_wqh;
    for (int i = tid; i < 288 * 12; i += 512) {
        int r = i / 12, q = i - r * 12;
        *(uint4*)(Wq + r * XS2 + q * 8) = wsrc[i];
    }
    __syncthreads();

    float acc[3][2][3][4];
#pragma unroll
    for (int jt = 0; jt < 3; jt++)
#pragma unroll
        for (int i = 0; i < 2; i++)
#pragma unroll
            for (int jj = 0; jj < 3; jj++)
#pragma unroll
                for (int r = 0; r < 4; r++) acc[jt][i][jj][r] = 0.f;

#pragma unroll
    for (int ks = 0; ks < 6; ks++) {
        int k0 = ks * 16;
        unsigned A[2][4];
#pragma unroll
        for (int i = 0; i < 2; i++) {
            const __half* base = Xs + (m0 + 16 * i + gid) * XS2 + k0 + 2 * tig;
            A[i][0] = *(const unsigned*)(base);
            A[i][1] = *(const unsigned*)(base + 8 * XS2);
            A[i][2] = *(const unsigned*)(base + 8);
            A[i][3] = *(const unsigned*)(base + 8 * XS2 + 8);
        }
#pragma unroll
        for (int jt = 0; jt < 3; jt++) {
            unsigned Bv[3][2];
#pragma unroll
            for (int jj = 0; jj < 3; jj++) {
                const __half* bb = Wq + (g0 + 24 * jt + 8 * jj + gid) * XS2 + k0 + 2 * tig;
                Bv[jj][0] = *(const unsigned*)(bb);
                Bv[jj][1] = *(const unsigned*)(bb + 8);
            }
#pragma unroll
            for (int i = 0; i < 2; i++)
#pragma unroll
                for (int jj = 0; jj < 3; jj++) mma16(acc[jt][i][jj], A[i], Bv[jj]);
        }
    }

    __half* ob = g_qkv16 + ((size_t)b * TT + t0) * 288;
#pragma unroll
    for (int jt = 0; jt < 3; jt++)
#pragma unroll
        for (int jj = 0; jj < 3; jj++) {
            int c = g0 + 24 * jt + 8 * jj + 2 * tig;
            float2 bv = *(const float2*)(bias + c);
#pragma unroll
            for (int i = 0; i < 2; i++) {
                int row = m0 + 16 * i + gid;
                __half2 lo = __floats2half2_rn(acc[jt][i][jj][0] + bv.x,
                                               acc[jt][i][jj][1] + bv.y);
                __half2 hi = __floats2half2_rn(acc[jt][i][jj][2] + bv.x,
                                               acc[jt][i][jj][3] + bv.y);
                *(__half2*)(ob + (size_t)row * 288 + c)       = lo;
                *(__half2*)(ob + (size_t)(row + 8) * 288 + c) = hi;
            }
        }
}

// =====================================================================
// Kernel 2 (FUSED): banded attention (all 3 heads) + out-proj + residual
// + LN1.  grid (T/64, B) = 256 blocks, 128 threads (4 warps).
// Head loop: stage Q/K/Vt per head, S via mma, softmax in regs,
// ctx slice -> smem Ctx[64][104].  Then oproj mma + LN1 epilogue.
// =====================================================================
#define QSTR 40
#define VSTR 136

__global__ __launch_bounds__(128, 1) void k_attn_oproj(const float* __restrict__ x,
                                                       const float* __restrict__ bo,
                                                       const float* __restrict__ g1,
                                                       const float* __restrict__ b1) {
    extern __shared__ char smraw[];
    __half* Qs  = (__half*)smraw;         // [64][40]
    __half* Ks  = Qs + 64 * QSTR;         // [128][40]
    __half* Vt  = Ks + 128 * QSTR;        // [32][136]
    __half* Ctx = Vt + 32 * VSTR;         // [64][104]
    __half* Wo  = Ctx + 64 * XS2;         // [96][104]
    __shared__ float BoS[96], G1S[96], B1S[96];

    int t0 = blockIdx.x * 64;
    int b  = blockIdx.y;
    int tid  = threadIdx.x;
    int lane = tid & 31;
    int w    = tid >> 5;
    int gid  = lane >> 2;
    int tig  = lane & 3;
    int m0a  = w * 16;          // query tile for attention phase
    int kbase = t0 - HW;

    const __half* qkvb = g_qkv16 + (size_t)b * TT * 288;

    // stage Wo once (consumed after the head loop; sync below covers it)
    const uint4* wsrc = (const uint4*)g_woh;
    for (int i = tid; i < 96 * 12; i += 128) {
        int r = i / 12, q = i - r * 12;
        *(uint4*)(Wo + r * XS2 + q * 8) = wsrc[i];
    }
    if (tid < 96) { BoS[tid] = bo[tid]; G1S[tid] = g1[tid]; B1S[tid] = b1[tid]; }

    for (int h = 0; h < NH; h++) {
        __syncthreads();   // Qs/Ks/Vt reusable (prev head consumers done)

        // stage Q [64][32]
        for (int i = tid; i < 64 * 4; i += 128) {
            int r = i >> 2, seg = i & 3;
            *(uint4*)(Qs + r * QSTR + seg * 8) =
                *(const uint4*)(qkvb + (size_t)(t0 + r) * 288 + h * HD + seg * 8);
        }
        // stage K [128][32]
        for (int i = tid; i < 128 * 4; i += 128) {
            int r = i >> 2, seg = i & 3;
            int s = kbase + r;
            uint4 v = make_uint4(0, 0, 0, 0);
            if (s >= 0 && s < TT)
                v = *(const uint4*)(qkvb + (size_t)s * 288 + 96 + h * HD + seg * 8);
            *(uint4*)(Ks + r * QSTR + seg * 8) = v;
        }
        // stage V^T [32][128]
        {
            int r = tid;
            int s = kbase + r;
            uint4 vv[4];
            if (s >= 0 && s < TT) {
#pragma unroll
                for (int seg = 0; seg < 4; seg++)
                    vv[seg] = *(const uint4*)(qkvb + (size_t)s * 288 + 192 + h * HD + seg * 8);
            } else {
#pragma unroll
                for (int seg = 0; seg < 4; seg++) vv[seg] = make_uint4(0, 0, 0, 0);
            }
            const __half* vh = (const __half*)vv;
#pragma unroll
            for (int f = 0; f < 32; f++) Vt[f * VSTR + r] = vh[f];
        }
        __syncthreads();

        // ---- S = Q @ K^T ----
        float s[16][4];
#pragma unroll
        for (int j = 0; j < 16; j++)
#pragma unroll
            for (int r = 0; r < 4; r++) s[j][r] = 0.f;

#pragma unroll
        for (int ks = 0; ks < 2; ks++) {
            int k0 = ks * 16;
            unsigned A[4];
            const __half* abase = Qs + (m0a + gid) * QSTR + k0 + 2 * tig;
            A[0] = *(const unsigned*)(abase);
            A[1] = *(const unsigned*)(abase + 8 * QSTR);
            A[2] = *(const unsigned*)(abase + 8);
            A[3] = *(const unsigned*)(abase + 8 * QSTR + 8);
#pragma unroll
            for (int j = 0; j < 16; j++) {
                unsigned Bv[2];
                const __half* bb = Ks + (8 * j + gid) * QSTR + k0 + 2 * tig;
                Bv[0] = *(const unsigned*)(bb);
                Bv[1] = *(const unsigned*)(bb + 8);
                mma16(s[j], A, Bv);
            }
        }

        // ---- softmax (band mask) ----
        const float scale = 0.17677669529663689f;
        int row0 = m0a + gid;
        int row1 = row0 + 8;
        float mx0 = -1e30f, mx1 = -1e30f;
#pragma unroll
        for (int j = 0; j < 16; j++) {
#pragma unroll
            for (int c = 0; c < 2; c++) {
                int col = 8 * j + 2 * tig + c;
                int key = kbase + col;
                bool in = (key >= 0) && (key < TT);
                bool v0 = in && (col >= row0) && (col <= row0 + 64);
                bool v1 = in && (col >= row1) && (col <= row1 + 64);
                s[j][c]     = v0 ? s[j][c] * scale     : -1e30f;
                s[j][c + 2] = v1 ? s[j][c + 2] * scale : -1e30f;
                mx0 = fmaxf(mx0, s[j][c]);
                mx1 = fmaxf(mx1, s[j][c + 2]);
            }
        }
        mx0 = fmaxf(mx0, __shfl_xor_sync(0xffffffffu, mx0, 1));
        mx0 = fmaxf(mx0, __shfl_xor_sync(0xffffffffu, mx0, 2));
        mx1 = fmaxf(mx1, __shfl_xor_sync(0xffffffffu, mx1, 1));
        mx1 = fmaxf(mx1, __shfl_xor_sync(0xffffffffu, mx1, 2));

        float sum0 = 0.f, sum1 = 0.f;
#pragma unroll
        for (int j = 0; j < 16; j++) {
            s[j][0] = __expf(s[j][0] - mx0);  sum0 += s[j][0];
            s[j][1] = __expf(s[j][1] - mx0);  sum0 += s[j][1];
            s[j][2] = __expf(s[j][2] - mx1);  sum1 += s[j][2];
            s[j][3] = __expf(s[j][3] - mx1);  sum1 += s[j][3];
        }
        sum0 += __shfl_xor_sync(0xffffffffu, sum0, 1);
        sum0 += __shfl_xor_sync(0xffffffffu, sum0, 2);
        sum1 += __shfl_xor_sync(0xffffffffu, sum1, 1);
        sum1 += __shfl_xor_sync(0xffffffffu, sum1, 2);
        float inv0 = 1.f / sum0, inv1 = 1.f / sum1;

        unsigned pa[8][4];
#pragma unroll
        for (int kt = 0; kt < 8; kt++) {
            __half2 a0 = __floats2half2_rn(s[2 * kt][0] * inv0,     s[2 * kt][1] * inv0);
            __half2 a1 = __floats2half2_rn(s[2 * kt][2] * inv1,     s[2 * kt][3] * inv1);
            __half2 a2 = __floats2half2_rn(s[2 * kt + 1][0] * inv0, s[2 * kt + 1][1] * inv0);
            __half2 a3 = __floats2half2_rn(s[2 * kt + 1][2] * inv1, s[2 * kt + 1][3] * inv1);
            pa[kt][0] = *reinterpret_cast<unsigned*>(&a0);
            pa[kt][1] = *reinterpret_cast<unsigned*>(&a1);
            pa[kt][2] = *reinterpret_cast<unsigned*>(&a2);
            pa[kt][3] = *reinterpret_cast<unsigned*>(&a3);
        }

        // ---- ctx = P @ V^T ----
        float o[4][4];
#pragma unroll
        for (int n = 0; n < 4; n++)
#pragma unroll
            for (int r = 0; r < 4; r++) o[n][r] = 0.f;

#pragma unroll
        for (int kt = 0; kt < 8; kt++) {
#pragma unroll
            for (int n = 0; n < 4; n++) {
                unsigned Bv[2];
                const __half* bb = Vt + (8 * n + gid) * VSTR + 16 * kt + 2 * tig;
                Bv[0] = *(const unsigned*)(bb);
                Bv[1] = *(const unsigned*)(bb + 8);
                mma16(o[n], pa[kt], Bv);
            }
        }

        // ctx slice -> smem (fp16)
#pragma unroll
        for (int n = 0; n < 4; n++) {
            int col = h * HD + 8 * n + 2 * tig;
            __half2 lo = __floats2half2_rn(o[n][0], o[n][1]);
            __half2 hi = __floats2half2_rn(o[n][2], o[n][3]);
            *(__half2*)(Ctx + row0 * XS2 + col) = lo;
            *(__half2*)(Ctx + row1 * XS2 + col) = hi;
        }
    }
    __syncthreads();   // Ctx complete, Wo staged

    // ---- out-proj: Y[64][96] = Ctx @ Wo^T ----
    // warp w: token rows m0 = (w&1)*32 (2 tiles), feat cols n0 = (w>>1)*48 (6 tiles)
    int m0 = (w & 1) * 32;
    int n0 = (w >> 1) * 48;
    float Y[2][6][4];
#pragma unroll
    for (int i = 0; i < 2; i++)
#pragma unroll
        for (int j = 0; j < 6; j++)
#pragma unroll
            for (int r = 0; r < 4; r++) Y[i][j][r] = 0.f;

#pragma unroll
    for (int ks = 0; ks < 6; ks++) {
        int k0 = ks * 16;
        unsigned A[2][4], Bv[6][2];
#pragma unroll
        for (int i = 0; i < 2; i++) {
            const __half* base = Ctx + (m0 + 16 * i + gid) * XS2 + k0 + 2 * tig;
            A[i][0] = *(const unsigned*)(base);
            A[i][1] = *(const unsigned*)(base + 8 * XS2);
            A[i][2] = *(const unsigned*)(base + 8);
            A[i][3] = *(const unsigned*)(base + 8 * XS2 + 8);
        }
#pragma unroll
        for (int j = 0; j < 6; j++) {
            const __half* bb = Wo + (n0 + 8 * j + gid) * XS2 + k0 + 2 * tig;
            Bv[j][0] = *(const unsigned*)(bb);
            Bv[j][1] = *(const unsigned*)(bb + 8);
        }
#pragma unroll
        for (int i = 0; i < 2; i++)
#pragma unroll
            for (int j = 0; j < 6; j++) mma16(Y[i][j], A[i], Bv[j]);
    }

    // dump Y -> fp32 smem (alias over dead buffers), LN1, write h1/h16
    __syncthreads();
    float* Ys = (float*)smraw;   // [64][101] = 25856 B < smem size
#pragma unroll
    for (int i = 0; i < 2; i++)
#pragma unroll
        for (int j = 0; j < 6; j++) {
            int row = m0 + 16 * i + gid;
            int col = n0 + 8 * j + 2 * tig;
            Ys[row * 101 + col]           = Y[i][j][0];
            Ys[row * 101 + col + 1]       = Y[i][j][1];
            Ys[(row + 8) * 101 + col]     = Y[i][j][2];
            Ys[(row + 8) * 101 + col + 1] = Y[i][j][3];
        }
    __syncthreads();

    if (tid < 64) {
        int t = tid;
        const float* xb = x + (size_t)b * CC * TT + t0 + t;
        float* yr = Ys + t * 101;
        float mu = 0.f;
#pragma unroll
        for (int c = 0; c < 96; c++) {
            float v = yr[c] + xb[(size_t)c * TT] + BoS[c];
            yr[c] = v;
            mu += v;
        }
        mu *= (1.f / 96.f);
        float var = 0.f;
#pragma unroll
        for (int c = 0; c < 96; c++) {
            float d = yr[c] - mu;
            var += d * d;
        }
        var *= (1.f / 96.f);
        float rs = rsqrtf(var + EPSL);

        float* hb = g_h1 + (size_t)b * CC * TT + t0 + t;
        unsigned hu[48];
#pragma unroll
        for (int c = 0; c < 96; c += 2) {
            float v0 = (yr[c] - mu) * rs * G1S[c] + B1S[c];
            float v1 = (yr[c + 1] - mu) * rs * G1S[c + 1] + B1S[c + 1];
            hb[(size_t)c * TT] = v0;
            hb[(size_t)(c + 1) * TT] = v1;
            __half2 p = __floats2half2_rn(v0, v1);
            hu[c >> 1] = *reinterpret_cast<unsigned*>(&p);
        }
        uint4* dst = (uint4*)(g_h16 + ((size_t)b * TT + t0 + t) * 96);
#pragma unroll
        for (int qq = 0; qq < 12; qq++)
            dst[qq] = make_uint4(hu[4 * qq], hu[4 * qq + 1], hu[4 * qq + 2], hu[4 * qq + 3]);
    }
}

// =====================================================================
// Kernel 3: FF (unchanged from R4-R6)
// =====================================================================
#define HS2 104
#define US2 72

__device__ __forceinline__ void stage_w(int jc, __half* W1d, __half* W2d, int tid) {
    const __half* w1h = g_w1h;
    const __half* w2h = g_w2h;
#pragma unroll
    for (int s = tid; s < 768; s += 512) {
        int r = s / 12, q = s - r * 12;
        cpa16(W1d + r * HS2 + q * 8, w1h + (size_t)(jc + r) * 96 + q * 8);
    }
#pragma unroll
    for (int s = tid; s < 768; s += 512) {
        int r = s >> 3, q = s & 7;
        cpa16(W2d + r * US2 + q * 8, w2h + (size_t)r * DFF + jc + q * 8);
    }
    cpa_commit();
}

__global__ __launch_bounds__(512, 1) void k_ff(const float* __restrict__ b1f,
                                               const float* __restrict__ b2f,
                                               const float* __restrict__ g2,
                                               const float* __restrict__ b2,
                                               const float* __restrict__ gf,
                                               const float* __restrict__ bf,
                                               float* __restrict__ out) {
    extern __shared__ char smraw[];
    __half* Hs  = (__half*)smraw;           // [128][104]
    __half* Us  = Hs + 128 * HS2;           // [128][72]
    __half* W1b = Us + 128 * US2;           // 2 x [64][104]
    __half* W2b = W1b + 2 * 64 * HS2;       // 2 x [96][72]
    __shared__ float B2F[96], G2S[96], B2S[96], GFS[96], BFS[96];

    int t0 = blockIdx.x * 128;
    int b  = blockIdx.y;
    int tid  = threadIdx.x;
    int lane = tid & 31;
    int w    = tid >> 5;
    int gid  = lane >> 2;
    int tig  = lane & 3;

    int m0u = (w & 3) * 32;
    int n0u = (w >> 2) * 16;
    int m0y = (w & 3) * 32;
    int n0y = (w >> 2) * 24;

    stage_w(0, W1b, W2b, tid);

    const uint4* hsrc = (const uint4*)(g_h16 + ((size_t)b * TT + t0) * 96);
    for (int i = tid; i < 128 * 12; i += 512) {
        int tok = i / 12, seg = i - tok * 12;
        *(uint4*)(Hs + tok * HS2 + seg * 8) = hsrc[i];
    }
    if (tid < 96) {
        B2F[tid] = b2f[tid]; G2S[tid] = g2[tid]; B2S[tid] = b2[tid];
        GFS[tid] = gf[tid];  BFS[tid] = bf[tid];
    }

    float Y[2][3][4];
#pragma unroll
    for (int i = 0; i < 2; i++)
#pragma unroll
        for (int j = 0; j < 3; j++)
#pragma unroll
            for (int r = 0; r < 4; r++) Y[i][j][r] = 0.f;

    for (int c = 0; c < 32; c++) {
        int jc = c * 64;
        __half* W1c = W1b + (c & 1) * 64 * HS2;
        __half* W2c = W2b + (c & 1) * 96 * US2;

        cpa_wait_all();
        __syncthreads();

        float ua[2][2][4];
#pragma unroll
        for (int i = 0; i < 2; i++)
#pragma unroll
            for (int j = 0; j < 2; j++)
#pragma unroll
                for (int r = 0; r < 4; r++) ua[i][j][r] = 0.f;

#pragma unroll
        for (int ks = 0; ks < 6; ks++) {
            int k0 = ks * 16;
            unsigned A[2][4], Bv[2][2];
#pragma unroll
            for (int i = 0; i < 2; i++) {
                const __half* base = Hs + (m0u + 16 * i + gid) * HS2 + k0 + 2 * tig;
                A[i][0] = *(const unsigned*)(base);
                A[i][1] = *(const unsigned*)(base + 8 * HS2);
                A[i][2] = *(const unsigned*)(base + 8);
                A[i][3] = *(const unsigned*)(base + 8 * HS2 + 8);
            }
#pragma unroll
            for (int j = 0; j < 2; j++) {
                const __half* bb = W1c + (n0u + 8 * j + gid) * HS2 + k0 + 2 * tig;
                Bv[j][0] = *(const unsigned*)(bb);
                Bv[j][1] = *(const unsigned*)(bb + 8);
            }
#pragma unroll
            for (int i = 0; i < 2; i++)
#pragma unroll
                for (int j = 0; j < 2; j++) mma16(ua[i][j], A[i], Bv[j]);
        }

#pragma unroll
        for (int j = 0; j < 2; j++) {
            float2 bv = *(const float2*)(b1f + jc + n0u + 8 * j + 2 * tig);
#pragma unroll
            for (int i = 0; i < 2; i++) {
                __half2 lo = __floats2half2_rn(fmaxf(ua[i][j][0] + bv.x, 0.f),
                                               fmaxf(ua[i][j][1] + bv.y, 0.f));
                __half2 hi = __floats2half2_rn(fmaxf(ua[i][j][2] + bv.x, 0.f),
                                               fmaxf(ua[i][j][3] + bv.y, 0.f));
                *(__half2*)(Us + (m0u + 16 * i + gid) * US2 + n0u + 8 * j + 2 * tig)     = lo;
                *(__half2*)(Us + (m0u + 16 * i + gid + 8) * US2 + n0u + 8 * j + 2 * tig) = hi;
            }
        }
        __syncthreads();

        if (c + 1 < 32)
            stage_w(jc + 64, W1b + ((c + 1) & 1) * 64 * HS2,
                    W2b + ((c + 1) & 1) * 96 * US2, tid);

#pragma unroll
        for (int ks = 0; ks < 4; ks++) {
            int k0 = ks * 16;
            unsigned A[2][4], Bv[3][2];
#pragma unroll
            for (int i = 0; i < 2; i++) {
                const __half* base = Us + (m0y + 16 * i + gid) * US2 + k0 + 2 * tig;
                A[i][0] = *(const unsigned*)(base);
                A[i][1] = *(const unsigned*)(base + 8 * US2);
                A[i][2] = *(const unsigned*)(base + 8);
                A[i][3] = *(const unsigned*)(base + 8 * US2 + 8);
            }
#pragma unroll
            for (int j = 0; j < 3; j++) {
                const __half* bb = W2c + (n0y + 8 * j + gid) * US2 + k0 + 2 * tig;
                Bv[j][0] = *(const unsigned*)(bb);
                Bv[j][1] = *(const unsigned*)(bb + 8);
            }
#pragma unroll
            for (int i = 0; i < 2; i++)
#pragma unroll
                for (int j = 0; j < 3; j++) mma16(Y[i][j], A[i], Bv[j]);
        }
    }

    __syncthreads();
    float* Ys = (float*)smraw;
#pragma unroll
    for (int i = 0; i < 2; i++)
#pragma unroll
        for (int j = 0; j < 3; j++) {
            int row = m0y + 16 * i + gid;
            int col = n0y + 8 * j + 2 * tig;
            Ys[row * 101 + col]           = Y[i][j][0];
            Ys[row * 101 + col + 1]       = Y[i][j][1];
            Ys[(row + 8) * 101 + col]     = Y[i][j][2];
            Ys[(row + 8) * 101 + col + 1] = Y[i][j][3];
        }
    __syncthreads();

    if (tid < 128) {
        int t = tid;
        const float* h1p = g_h1 + (size_t)b * CC * TT + t0 + t;
        float* yr = Ys + t * 101;
        float mu = 0.f;
#pragma unroll
        for (int c = 0; c < 96; c++) {
            float v = yr[c] + h1p[(size_t)c * TT] + B2F[c];
            yr[c] = v;
            mu += v;
        }
        mu *= (1.f / 96.f);
        float var = 0.f;
#pragma unroll
        for (int c = 0; c < 96; c++) {
            float d = yr[c] - mu;
            var += d * d;
        }
        var *= (1.f / 96.f);
        float rs1 = rsqrtf(var + EPSL);

        float m2 = 0.f, s2 = 0.f;
#pragma unroll
        for (int c = 0; c < 96; c++) {
            float z = (yr[c] - mu) * rs1 * G2S[c] + B2S[c];
            yr[c] = z;
            m2 += z;
            s2 += z * z;
        }
        m2 *= (1.f / 96.f);
        float var2 = s2 * (1.f / 96.f) - m2 * m2;
        float rs2 = rsqrtf(var2 + EPSL);

        float* ob = out + (size_t)b * CC * TT + t0 + t;
        for (int c = 0; c < 96; c++)
            ob[(size_t)c * TT] = (yr[c] - m2) * rs2 * GFS[c] + BFS[c];
    }
}

// =====================================================================
extern "C" void kernel_launch(void* const* d_in, const int* in_sizes, int n_in,
                              void* d_out, int out_size) {
    const float* x     = (const float*)d_in[0];
    const float* w_qkv = (const float*)d_in[1];
    const float* b_qkv = (const float*)d_in[2];
    const float* w_out = (const float*)d_in[3];
    const float* b_out = (const float*)d_in[4];
    const float* ln1_g = (const float*)d_in[5];
    const float* ln1_b = (const float*)d_in[6];
    const float* w_ff1 = (const float*)d_in[7];
    const float* b_ff1 = (const float*)d_in[8];
    const float* w_ff2 = (const float*)d_in[9];
    const float* b_ff2 = (const float*)d_in[10];
    const float* ln2_g = (const float*)d_in[11];
    const float* ln2_b = (const float*)d_in[12];
    const float* lnf_g = (const float*)d_in[13];
    const float* lnf_b = (const float*)d_in[14];
    float* out = (float*)d_out;

    const int smemQ = (128 * XS2 + 288 * XS2) * 2;                          // 86528
    const int smemAO = (64 * QSTR + 128 * QSTR + 32 * VSTR + 64 * XS2 + 96 * XS2) * 2;  // 57344
    const int smemF = (128 * HS2 + 128 * US2 + 2 * 64 * HS2 + 2 * 96 * US2) * 2;        // 99328

    cudaFuncSetAttribute(k_qkv,        cudaFuncAttributeMaxDynamicSharedMemorySize, smemQ);
    cudaFuncSetAttribute(k_attn_oproj, cudaFuncAttributeMaxDynamicSharedMemorySize, smemAO);
    cudaFuncSetAttribute(k_ff,         cudaFuncAttributeMaxDynamicSharedMemorySize, smemF);

    k_prep<<<PREP_BLKS + 64 * 3 * BB, 256>>>(w_ff1, w_ff2, w_qkv, w_out, x);
    k_qkv<<<dim3(TT / 128, BB), 512, smemQ>>>(b_qkv);
    k_attn_oproj<<<dim3(TT / 64, BB), 128, smemAO>>>(x, b_out, ln1_g, ln1_b);
    k_ff<<<dim3(TT / 128, BB), 512, smemF>>>(b_ff1, b_ff2, ln2_g, ln2_b,
                                             lnf_g, lnf_b, out);
}